// round 5
// baseline (speedup 1.0000x reference)
#include <cuda_runtime.h>
#include <math.h>
#include <stdint.h>

#define NB 128
#define NT 32
#define NIN 512
#define NH 512
#define NM 16
#define NWC 20
#define NR 4
#define NRW 80
#define NNIN 592
#define NIF 163
#define NIFP 192
#define CLIPV 20.0f
#define EPSF 1e-6f
#define DELTAF 5e-6f

// ---------------- persistent state (device globals; allocation-free) ----------
__device__ float g_h[2][2][2][NB][NH];   // [parity][layer][cell][b][h]
__device__ float g_c[2][2][NB][NH];      // [layer][cell][b][h]
__device__ float g_inp[NB][NNIN];        // concat(out, read_vecs)
__device__ float g_ifc[NB][NIFP];        // iface projection result
__device__ float g_mem[2][NB][NM][NWC];
__device__ float g_link[2][NB][NM][NM];
__device__ float g_prec[2][NB][NM];
__device__ float g_rw[2][NB][NR][NM];
__device__ float g_ww[2][NB][NM];
__device__ float g_usage[2][NB][NM];

// ---------------- converted (tf32 hi/lo split, fragment-swizzled) weights ----
// layout: [nfrag][k8][hl 2][lane 32][reg 4]  (one float4 per (nfrag,k8,hl,lane))
__device__ float g_W00[128 * 128 * 256];   // l0 cell0: 2048 x 1024
__device__ float g_W01[128 * 138 * 256];   // l1 cell0: 2048 x 1104
__device__ float g_W10[128 * 128 * 256];   // l0 cell1
__device__ float g_W11[128 * 128 * 256];   // l1 cell1
__device__ float g_Wif[2 * 12 * 64 * 256]; // iface: 192(pad) x 512, per layer
__device__ float g_Wo[32 * 74 * 256];      // out: 512 x 592
__device__ float g_bc[2 * 2 * 2048];       // gate-reordered biases [l][cell][n']

__device__ __forceinline__ float sigf(float x) { return 1.f / (1.f + expf(-x)); }
__device__ __forceinline__ float softplusf(float x) {
    return fmaxf(x, 0.f) + log1pf(expf(-fabsf(x)));
}
__device__ __forceinline__ float clipf(float x) {
    return fminf(fmaxf(x, -CLIPV), CLIPV);
}
__device__ __forceinline__ float tf32r(float x) {
    uint32_t u;
    asm("cvt.rna.tf32.f32 %0, %1;" : "=r"(u) : "f"(x));
    return __uint_as_float(u);
}

// ---------------- init: zero all state --------------------------------------
__global__ void initk() {
    long i0 = blockIdx.x * (long)blockDim.x + threadIdx.x;
    long st = (long)gridDim.x * blockDim.x;
    for (long i = i0; i < 2L * 2 * 2 * NB * NH; i += st) ((float*)g_h)[i] = 0.f;
    for (long i = i0; i < 2L * 2 * NB * NH; i += st) ((float*)g_c)[i] = 0.f;
    for (long i = i0; i < (long)NB * NNIN; i += st) ((float*)g_inp)[i] = 0.f;
    for (long i = i0; i < 2L * NB * NM * NWC; i += st) ((float*)g_mem)[i] = 0.f;
    for (long i = i0; i < 2L * NB * NM * NM; i += st) ((float*)g_link)[i] = 0.f;
    for (long i = i0; i < 2L * NB * NM; i += st) {
        ((float*)g_prec)[i] = 0.f;
        ((float*)g_ww)[i] = 0.f;
        ((float*)g_usage)[i] = 0.f;
    }
    for (long i = i0; i < 2L * NB * NR * NM; i += st) ((float*)g_rw)[i] = 0.f;
}

// ---------------- weight conversion pre-pass ---------------------------------
// one thread per (nfrag, k8, lane); gathers 4 regs, splits hi/lo, stores 2 float4.
__global__ void prep(
    const float* __restrict__ W1, int ld1, int K1,
    const float* __restrict__ W2, int ld2, int K2,
    float* __restrict__ dst, int gateReorder, int nReal, int nPad)
{
    const int K8 = (K1 + K2) >> 3;
    int idx = blockIdx.x * blockDim.x + threadIdx.x;
    int total = (nPad >> 4) * K8 * 32;
    if (idx >= total) return;
    int lane = idx & 31;
    int k8 = (idx >> 5) % K8;
    int nfrag = (idx >> 5) / K8;
    int r0 = lane >> 2, c0 = lane & 3;
    float4 hi, lo;
    float* ph = (float*)&hi;
    float* pl = (float*)&lo;
#pragma unroll
    for (int reg = 0; reg < 4; ++reg) {
        int r = nfrag * 16 + r0 + 8 * (reg & 1);
        int k = k8 * 8 + c0 + 4 * (reg >> 1);
        float x = 0.f;
        int row;
        if (gateReorder) { int j = r >> 2, g = r & 3; row = g * NH + j; }
        else row = r;
        if (row < nReal)
            x = (k < K1) ? W1[(size_t)row * ld1 + k]
                         : W2[(size_t)row * ld2 + (k - K1)];
        float h = tf32r(x);
        ph[reg] = h;
        pl[reg] = tf32r(x - h);
    }
    ((float4*)dst)[((size_t)(nfrag * K8 + k8) * 2 + 0) * 32 + lane] = hi;
    ((float4*)dst)[((size_t)(nfrag * K8 + k8) * 2 + 1) * 32 + lane] = lo;
}

__global__ void prepbias(const float* bih0, const float* bhh0,
                         const float* bih1, const float* bhh1,
                         float* bc)
{
    int i = blockIdx.x * blockDim.x + threadIdx.x;
    if (i >= 2 * 2 * 2048) return;
    int n = i & 2047;
    int cell = (i >> 11) & 1;
    int l = i >> 12;
    int j = n >> 2, g = n & 3;
    const float* bi = cell ? bih1 : bih0;
    const float* bh = cell ? bhh1 : bhh0;
    bc[i] = bi[(size_t)l * 4 * NH + g * NH + j] + bh[(size_t)l * 4 * NH + g * NH + j];
}

// ---------------- compensated tf32 tensor-core GEMM --------------------------
// C[n', b] = W[n'] . concat(A1,A2)[b]  (block: 32 n' x 64 batch; 4 warps)
// 3-term split: Whi*Bhi + Wlo*Bhi + Whi*Blo  (fp32-class accuracy)
// MODE 0: LSTM epilogue (rows gate-interleaved: n' = j*4+g); MODE 1: linear+bias
__device__ __forceinline__ void mma_tf32(float c[4], float4 w, float b0, float b1) {
    asm volatile(
        "mma.sync.aligned.m16n8k8.row.col.f32.tf32.tf32.f32 "
        "{%0,%1,%2,%3}, {%4,%5,%6,%7}, {%8,%9}, {%0,%1,%2,%3};"
        : "+f"(c[0]), "+f"(c[1]), "+f"(c[2]), "+f"(c[3])
        : "r"(__float_as_uint(w.x)), "r"(__float_as_uint(w.y)),
          "r"(__float_as_uint(w.z)), "r"(__float_as_uint(w.w)),
          "r"(__float_as_uint(b0)), "r"(__float_as_uint(b1)));
}

__device__ __forceinline__ float4 ldA4(const float* __restrict__ A1, int sA1, int K1,
                                       const float* __restrict__ A2, int sA2,
                                       int b, int k)
{
    const float* p = (k < K1) ? A1 + (size_t)b * sA1 + k
                              : A2 + (size_t)b * sA2 + (k - K1);
    return *(const float4*)p;
}

template <int MODE>
__global__ __launch_bounds__(128) void tcgemm(
    const float* __restrict__ A1, int sA1, int K1,
    const float* __restrict__ A2, int sA2, int K2,
    const float* __restrict__ Wswz,
    const float* __restrict__ bias,
    int nReal,
    float* __restrict__ cio,
    float* __restrict__ outp, int sOut,
    float* __restrict__ clipOut)
{
    __shared__ float sbuf[4224];
    const int K = K1 + K2;
    const int nch = K >> 4;
    const int K8 = K >> 3;
    const int tid = threadIdx.x;
    const int lane = tid & 31, warp = tid >> 5;
    const int wn = warp & 1, wb = warp >> 1;
    const int nblk = blockIdx.x;
    const int b0 = blockIdx.y * 64;

    float acc[4][4];
#pragma unroll
    for (int j = 0; j < 4; ++j)
#pragma unroll
        for (int q = 0; q < 4; ++q) acc[j][q] = 0.f;

    // W pointer: stride per k8 is 64 float4 (hi 32 + lo 32)
    const float4* Wp = (const float4*)Wswz + (size_t)(nblk * 2 + wn) * K8 * 64 + lane;

    const int abl0 = tid >> 2;     // 0..31 (batch-local base)
    const int akq = tid & 3;       // k quad within 16-chunk
    const int k8l = akq >> 1, regl = akq & 1;

    float4 arn[2];
    float4 wr[2][2], wrn[2][2];    // [k8][hi/lo]

    // prologue: load + stage chunk 0
    {
#pragma unroll
        for (int v = 0; v < 2; ++v) {
            float4 a = ldA4(A1, sA1, K1, A2, sA2, b0 + abl0 + v * 32, akq * 4);
            int bl = abl0 + v * 32;
            int base = ((k8l * 8 + (bl >> 3)) * 2 + regl) * 32 + (bl & 7) * 4;
            float hx = tf32r(a.x), hy = tf32r(a.y), hz = tf32r(a.z), hw = tf32r(a.w);
            *(float4*)(sbuf + base) = make_float4(hx, hy, hz, hw);
            *(float4*)(sbuf + base + 1024) =
                make_float4(tf32r(a.x - hx), tf32r(a.y - hy),
                            tf32r(a.z - hz), tf32r(a.w - hw));
        }
        wr[0][0] = Wp[0];      wr[0][1] = Wp[32];
        wr[1][0] = Wp[64];     wr[1][1] = Wp[96];
    }
    __syncthreads();

    for (int ch = 0; ch < nch; ++ch) {
        const int cur = ch & 1;
        if (ch + 1 < nch) {
#pragma unroll
            for (int v = 0; v < 2; ++v)
                arn[v] = ldA4(A1, sA1, K1, A2, sA2, b0 + abl0 + v * 32,
                              (ch + 1) * 16 + akq * 4);
            const float4* Wn = Wp + (size_t)(ch + 1) * 2 * 64;
            wrn[0][0] = Wn[0];   wrn[0][1] = Wn[32];
            wrn[1][0] = Wn[64];  wrn[1][1] = Wn[96];
        }
#pragma unroll
        for (int k8 = 0; k8 < 2; ++k8) {
            float4 whi = wr[k8][0], wlo = wr[k8][1];
#pragma unroll
            for (int j = 0; j < 4; ++j) {
                int bb8 = wb * 4 + j;
                int rb = cur * 2048 + ((k8 * 8 + bb8) * 2) * 32;
                float bhi0 = sbuf[rb + lane];
                float bhi1 = sbuf[rb + 32 + lane];
                float blo0 = sbuf[rb + 1024 + lane];
                float blo1 = sbuf[rb + 1056 + lane];
                mma_tf32(acc[j], whi, bhi0, bhi1);
                mma_tf32(acc[j], wlo, bhi0, bhi1);
                mma_tf32(acc[j], whi, blo0, blo1);
            }
        }
        if (ch + 1 < nch) {
            const int nxt = cur ^ 1;
#pragma unroll
            for (int v = 0; v < 2; ++v) {
                int bl = abl0 + v * 32;
                int base = nxt * 2048 + ((k8l * 8 + (bl >> 3)) * 2 + regl) * 32 + (bl & 7) * 4;
                float4 a = arn[v];
                float hx = tf32r(a.x), hy = tf32r(a.y), hz = tf32r(a.z), hw = tf32r(a.w);
                *(float4*)(sbuf + base) = make_float4(hx, hy, hz, hw);
                *(float4*)(sbuf + base + 1024) =
                    make_float4(tf32r(a.x - hx), tf32r(a.y - hy),
                                tf32r(a.z - hz), tf32r(a.w - hw));
            }
#pragma unroll
            for (int k8 = 0; k8 < 2; ++k8) {
                wr[k8][0] = wrn[k8][0];
                wr[k8][1] = wrn[k8][1];
            }
        }
        __syncthreads();
    }

    // ---- epilogue: transpose C fragments through shared ----
    const int CP = 66;
    {
        int r = lane >> 2;
        int cc = (lane & 3) * 2;
#pragma unroll
        for (int j = 0; j < 4; ++j) {
            int bl = wb * 32 + j * 8 + cc;
            int nl = wn * 16 + r;
            sbuf[nl * CP + bl] = acc[j][0];
            sbuf[nl * CP + bl + 1] = acc[j][1];
            sbuf[(nl + 8) * CP + bl] = acc[j][2];
            sbuf[(nl + 8) * CP + bl + 1] = acc[j][3];
        }
    }
    __syncthreads();

    if (MODE == 0) {
        // 8 j x 64 bl = 512 elements
#pragma unroll
        for (int i = 0; i < 4; ++i) {
            int pair = i * 128 + tid;
            int j = pair & 7, bl = pair >> 3;
            int jg = nblk * 8 + j;
            int b = b0 + bl;
            float gi = sbuf[(j * 4 + 0) * CP + bl] + bias[nblk * 32 + j * 4 + 0];
            float gf = sbuf[(j * 4 + 1) * CP + bl] + bias[nblk * 32 + j * 4 + 1];
            float gg = sbuf[(j * 4 + 2) * CP + bl] + bias[nblk * 32 + j * 4 + 2];
            float go = sbuf[(j * 4 + 3) * CP + bl] + bias[nblk * 32 + j * 4 + 3];
            float cold = cio[(size_t)b * NH + jg];
            float cn = sigf(gf) * cold + sigf(gi) * tanhf(gg);
            float hn = sigf(go) * tanhf(cn);
            cio[(size_t)b * NH + jg] = cn;
            outp[(size_t)b * sOut + jg] = hn;
            if (clipOut) clipOut[(size_t)b * NNIN + jg] = clipf(hn);
        }
    } else {
        // 32 n x 64 bl = 2048 elements  (R4 bug: was 512)
#pragma unroll
        for (int i = 0; i < 16; ++i) {
            int pair = i * 128 + tid;
            int n = pair & 31, bl = pair >> 5;
            int ng = nblk * 32 + n;
            if (ng < nReal) {
                int b = b0 + bl;
                outp[(size_t)b * sOut + ng] = sbuf[n * CP + bl] + bias[ng];
            }
        }
    }
}

// ---------------- DNC memory step (iface precomputed) ------------------------
__global__ __launch_bounds__(128) void memstep(
    const float* __restrict__ ifcg,   // [NB][NIFP]
    float* __restrict__ memg, float* __restrict__ linkg,
    float* __restrict__ precg, float* __restrict__ rwg,
    float* __restrict__ wwg, float* __restrict__ usg,
    float* __restrict__ inp)
{
    const int RS = 80, WK = 84, WS = 104, ER = 105, WV = 125,
              FG = 145, AG = 149, WG = 150, RM = 151;
    const int b = blockIdx.x;
    const int tid = threadIdx.x;

    __shared__ float ifc[NIF];
    __shared__ float sm[NM * NWC];
    __shared__ float sl[NM * NM];
    __shared__ float sp[NM], srw[NR * NM], sww[NM], sus[NM];
    __shared__ float wcw[NM], alo[NM];
    __shared__ float rcw[NR * NM], fwd[NR * NM], bwd[NR * NM];

    for (int i = tid; i < NIF; i += 128) ifc[i] = ifcg[b * NIFP + i];
    for (int i = tid; i < NM * NWC; i += 128) sm[i] = memg[b * NM * NWC + i];
    for (int i = tid; i < NM * NM; i += 128) sl[i] = linkg[b * NM * NM + i];
    if (tid < NM) {
        sp[tid] = precg[b * NM + tid];
        sww[tid] = wwg[b * NM + tid];
        sus[tid] = usg[b * NM + tid];
    }
    if (tid >= 32 && tid < 32 + NR * NM) srw[tid - 32] = rwg[b * NR * NM + tid - 32];
    __syncthreads();

    // usage update (OLD ww, OLD rw)
    if (tid < NM) {
        int m = tid;
        float uu = sus[m] + (1.f - sus[m]) * sww[m];
        float psi = 1.f;
#pragma unroll
        for (int r = 0; r < NR; ++r)
            psi *= 1.f - sigf(ifc[FG + r]) * srw[r * NM + m];
        sus[m] = uu * psi;
    }
    __syncthreads();

    // write content weights (cosine on OLD memory)
    if (tid < NM) {
        int m = tid;
        float kn2 = 0.f, dot = 0.f, mn2 = 0.f;
#pragma unroll
        for (int w = 0; w < NWC; ++w) {
            float kv = tanhf(ifc[WK + w]);
            float mv = sm[m * NWC + w];
            kn2 = fmaf(kv, kv, kn2);
            mn2 = fmaf(mv, mv, mn2);
            dot = fmaf(kv, mv, dot);
        }
        wcw[m] = dot / ((sqrtf(kn2) + EPSF) * (sqrtf(mn2) + EPSF));
    }
    __syncthreads();
    if (tid == 0) {
        float str = softplusf(ifc[WS]);
        float mx = -1e30f;
        for (int m = 0; m < NM; ++m) { wcw[m] *= str; mx = fmaxf(mx, wcw[m]); }
        float s = 0.f;
        for (int m = 0; m < NM; ++m) { wcw[m] = expf(wcw[m] - mx); s += wcw[m]; }
        float inv = 1.f / s;
        for (int m = 0; m < NM; ++m) wcw[m] *= inv;
    }
    // allocation weights (stable ascending argsort of u)
    if (tid == 32) {
        float u[NM]; int idx[NM];
        for (int m = 0; m < NM; ++m) { u[m] = DELTAF + (1.f - DELTAF) * sus[m]; idx[m] = m; }
        for (int i = 1; i < NM; ++i) {
            float kv = u[i]; int ki = idx[i]; int j = i;
            while (j > 0 && u[j - 1] > kv) { u[j] = u[j - 1]; idx[j] = idx[j - 1]; --j; }
            u[j] = kv; idx[j] = ki;
        }
        float prod = 1.f;
        for (int j = 0; j < NM; ++j) { alo[idx[j]] = (1.f - u[j]) * prod; prod *= u[j]; }
    }
    __syncthreads();

    // new write weights
    if (tid < NM) {
        float ag = sigf(ifc[AG]), wg = sigf(ifc[WG]);
        sww[tid] = wg * (ag * alo[tid] + (1.f - ag) * wcw[tid]);
    }
    __syncthreads();

    // memory write
    for (int i = tid; i < NM * NWC; i += 128) {
        int m = i / NWC, w = i % NWC;
        float e = sigf(ifc[ER + w]);
        float v = tanhf(ifc[WV + w]);
        sm[i] = sm[i] * (1.f - sww[m] * e) + sww[m] * v;
    }
    __syncthreads();

    // link update (NEW ww, OLD prec)
    for (int i = tid; i < NM * NM; i += 128) {
        int ii = i >> 4, jj = i & 15;
        sl[i] = (ii == jj) ? 0.f
                           : (1.f - sww[ii] - sww[jj]) * sl[i] + sww[ii] * sp[jj];
    }
    __syncthreads();

    // precedence
    if (tid < NM) {
        float s = 0.f;
#pragma unroll
        for (int m = 0; m < NM; ++m) s += sww[m];
        sp[tid] = (1.f - s) * sp[tid] + sww[tid];
    }
    __syncthreads();

    // read content weights (cosine on NEW memory)
    if (tid < NR * NM) {
        int r = tid >> 4, m = tid & 15;
        float kn2 = 0.f, dot = 0.f, mn2 = 0.f;
#pragma unroll
        for (int w = 0; w < NWC; ++w) {
            float kv = tanhf(ifc[r * NWC + w]);
            float mv = sm[m * NWC + w];
            kn2 = fmaf(kv, kv, kn2);
            mn2 = fmaf(mv, mv, mn2);
            dot = fmaf(kv, mv, dot);
        }
        rcw[tid] = dot / ((sqrtf(kn2) + EPSF) * (sqrtf(mn2) + EPSF));
    }
    __syncthreads();
    if (tid < NR) {
        int r = tid;
        float str = softplusf(ifc[RS + r]);
        float mx = -1e30f;
        for (int m = 0; m < NM; ++m) { rcw[r * NM + m] *= str; mx = fmaxf(mx, rcw[r * NM + m]); }
        float s = 0.f;
        for (int m = 0; m < NM; ++m) { rcw[r * NM + m] = expf(rcw[r * NM + m] - mx); s += rcw[r * NM + m]; }
        float inv = 1.f / s;
        for (int m = 0; m < NM; ++m) rcw[r * NM + m] *= inv;
    }
    __syncthreads();

    // forward / backward (NEW link, OLD rw)
    if (tid < NR * NM) {
        int r = tid >> 4, q = tid & 15;
        float f = 0.f, bb = 0.f;
#pragma unroll
        for (int j = 0; j < NM; ++j) {
            f = fmaf(sl[q * NM + j], srw[r * NM + j], f);
            bb = fmaf(srw[r * NM + j], sl[j * NM + q], bb);
        }
        fwd[tid] = f;
        bwd[tid] = bb;
    }
    __syncthreads();

    // new read weights (mode softmax over 3)
    if (tid < NR * NM) {
        int r = tid >> 4;
        float e0 = ifc[RM + r * 3 + 0], e1 = ifc[RM + r * 3 + 1], e2 = ifc[RM + r * 3 + 2];
        float mx = fmaxf(e0, fmaxf(e1, e2));
        float x0 = expf(e0 - mx), x1 = expf(e1 - mx), x2 = expf(e2 - mx);
        float inv = 1.f / (x0 + x1 + x2);
        srw[tid] = (x0 * bwd[tid] + x1 * fwd[tid] + x2 * rcw[tid]) * inv;
    }
    __syncthreads();

    // read vectors -> g_inp[:, 512:592]
    if (tid < NRW) {
        int r = tid / NWC, w = tid % NWC;
        float s = 0.f;
#pragma unroll
        for (int m = 0; m < NM; ++m) s = fmaf(srw[r * NM + m], sm[m * NWC + w], s);
        inp[(size_t)b * NNIN + NIN + tid] = s;
    }

    // write back state
    for (int i = tid; i < NM * NWC; i += 128) memg[b * NM * NWC + i] = sm[i];
    for (int i = tid; i < NM * NM; i += 128) linkg[b * NM * NM + i] = sl[i];
    if (tid < NM) {
        precg[b * NM + tid] = sp[tid];
        wwg[b * NM + tid] = sww[tid];
        usg[b * NM + tid] = sus[tid];
    }
    if (tid >= 32 && tid < 32 + NR * NM) rwg[b * NR * NM + tid - 32] = srw[tid - 32];
}

// ---------------- host driver ------------------------------------------------
static inline int prepBlocks(int nPad, int K) {
    long total = (long)(nPad >> 4) * (K >> 3) * 32;
    return (int)((total + 255) / 256);
}

extern "C" void kernel_launch(void* const* d_in, const int* in_sizes, int n_in,
                              void* d_out, int out_size)
{
    const float* x      = (const float*)d_in[0];
    const float* W_ih0  = (const float*)d_in[1];
    const float* W_hh0  = (const float*)d_in[2];
    const float* b_ih0  = (const float*)d_in[3];
    const float* b_hh0  = (const float*)d_in[4];
    const float* W_ih1  = (const float*)d_in[5];
    const float* W_hh1  = (const float*)d_in[6];
    const float* b_ih1  = (const float*)d_in[7];
    const float* b_hh1  = (const float*)d_in[8];
    const float* W_if   = (const float*)d_in[9];
    const float* b_if   = (const float*)d_in[10];
    const float* W_out  = (const float*)d_in[11];
    const float* b_out  = (const float*)d_in[12];
    float* y = (float*)d_out;

    float *ph, *pc, *pinp, *pifc, *pmem, *plink, *pprec, *prw, *pww, *pus;
    float *pW00, *pW01, *pW10, *pW11, *pWif, *pWo, *pbc;
    cudaGetSymbolAddress((void**)&ph,   g_h);
    cudaGetSymbolAddress((void**)&pc,   g_c);
    cudaGetSymbolAddress((void**)&pinp, g_inp);
    cudaGetSymbolAddress((void**)&pifc, g_ifc);
    cudaGetSymbolAddress((void**)&pmem, g_mem);
    cudaGetSymbolAddress((void**)&plink,g_link);
    cudaGetSymbolAddress((void**)&pprec,g_prec);
    cudaGetSymbolAddress((void**)&prw,  g_rw);
    cudaGetSymbolAddress((void**)&pww,  g_ww);
    cudaGetSymbolAddress((void**)&pus,  g_usage);
    cudaGetSymbolAddress((void**)&pW00, g_W00);
    cudaGetSymbolAddress((void**)&pW01, g_W01);
    cudaGetSymbolAddress((void**)&pW10, g_W10);
    cudaGetSymbolAddress((void**)&pW11, g_W11);
    cudaGetSymbolAddress((void**)&pWif, g_Wif);
    cudaGetSymbolAddress((void**)&pWo,  g_Wo);
    cudaGetSymbolAddress((void**)&pbc,  g_bc);

    auto hbuf = [&](int p, int l, int s) {
        return ph + (((size_t)p * 2 + l) * 2 + s) * NB * NH;
    };
    auto cbuf = [&](int l, int s) { return pc + ((size_t)l * 2 + s) * NB * NH; };

    initk<<<512, 256>>>();

    // ---- weight conversion pre-pass ----
    prep<<<prepBlocks(2048, 1024), 256>>>(W_ih0, NNIN, 512, W_hh0, NH, 512,
                                          pW00, 1, 2048, 2048);
    prep<<<prepBlocks(2048, 1104), 256>>>(W_ih0 + (size_t)4 * NH * NNIN, NNIN, 592,
                                          W_hh0 + (size_t)4 * NH * NH, NH, 512,
                                          pW01, 1, 2048, 2048);
    prep<<<prepBlocks(2048, 1024), 256>>>(W_ih1, NH, 512, W_hh1, NH, 512,
                                          pW10, 1, 2048, 2048);
    prep<<<prepBlocks(2048, 1024), 256>>>(W_ih1 + (size_t)4 * NH * NH, NH, 512,
                                          W_hh1 + (size_t)4 * NH * NH, NH, 512,
                                          pW11, 1, 2048, 2048);
    prep<<<prepBlocks(192, 512), 256>>>(W_if, NH, 512, W_if, NH, 0,
                                        pWif, 0, NIF, 192);
    prep<<<prepBlocks(192, 512), 256>>>(W_if + (size_t)NIF * NH, NH, 512,
                                        W_if + (size_t)NIF * NH, NH, 0,
                                        pWif + (size_t)12 * 64 * 256, 0, NIF, 192);
    prep<<<prepBlocks(512, 592), 256>>>(W_out, NNIN, 592, W_out, NNIN, 0,
                                        pWo, 0, 512, 512);
    prepbias<<<(2 * 2 * 2048 + 255) / 256, 256>>>(b_ih0, b_hh0, b_ih1, b_hh1, pbc);

    const float* Wc0[2] = {pW00, pW01};
    const float* Wc1[2] = {pW10, pW11};

    const dim3 gCell(64, 2);
    const dim3 gIf(6, 2);
    const dim3 gOut(16, 2);

    for (int t = 0; t < NT; ++t) {
        const int p = t & 1;
        for (int l = 0; l < 2; ++l) {
            // ---- cell 0 ----
            const float* A1; int sA1, K1;
            if (l == 0) { A1 = x + (size_t)t * NIN; sA1 = NT * NIN; K1 = NIN; }
            else        { A1 = pinp; sA1 = NNIN; K1 = NNIN; }
            tcgemm<0><<<gCell, 128>>>(
                A1, sA1, K1,
                hbuf(p, l, 0), NH, NH,
                Wc0[l],
                pbc + (size_t)(l * 2 + 0) * 2048,
                2048,
                cbuf(l, 0),
                hbuf(p ^ 1, l, 0), NH,
                nullptr);
            // ---- cell 1 ----
            tcgemm<0><<<gCell, 128>>>(
                hbuf(p ^ 1, l, 0), NH, NH,
                hbuf(p, l, 1), NH, NH,
                Wc1[l],
                pbc + (size_t)(l * 2 + 1) * 2048,
                2048,
                cbuf(l, 1),
                hbuf(p ^ 1, l, 1), NH,
                pinp);
            // ---- iface projection ----
            tcgemm<1><<<gIf, 128>>>(
                pinp, NNIN, 512,
                pinp, NNIN, 0,
                pWif + (size_t)l * 12 * 64 * 256,
                b_if + (size_t)l * NIF,
                NIF,
                nullptr,
                pifc, NIFP,
                nullptr);
            // ---- memory step ----
            memstep<<<NB, 128>>>(
                pifc,
                pmem + (size_t)l * NB * NM * NWC,
                plink + (size_t)l * NB * NM * NM,
                pprec + (size_t)l * NB * NM,
                prw + (size_t)l * NB * NR * NM,
                pww + (size_t)l * NB * NM,
                pus + (size_t)l * NB * NM,
                pinp);
        }
        // ---- output projection ----
        tcgemm<1><<<gOut, 128>>>(
            pinp, NNIN, 592,
            pinp, NNIN, 0,
            pWo,
            b_out,
            512,
            nullptr,
            y + (size_t)t * NIN, NT * NIN,
            nullptr);
    }
}

// round 6
// speedup vs baseline: 1.5902x; 1.5902x over previous
#include <cuda_runtime.h>
#include <cuda_bf16.h>
#include <math.h>
#include <stdint.h>

#define NB 128
#define NT 32
#define NIN 512
#define NH 512
#define NM 16
#define NWC 20
#define NR 4
#define NRW 80
#define NNIN 592
#define NIF 163
#define NIFP 192
#define CLIPV 20.0f
#define EPSF 1e-6f
#define DELTAF 5e-6f

// ---------------- persistent state (device globals; allocation-free) ----------
__device__ float g_h[2][2][2][NB][NH];   // [parity][layer][cell][b][h]
__device__ float g_c[2][2][NB][NH];      // [layer][cell][b][h]
__device__ float g_inp[NB][NNIN];        // concat(out, read_vecs)
__device__ float g_ifc[NB][NIFP];        // iface projection result
__device__ float g_mem[2][NB][NM][NWC];
__device__ float g_link[2][NB][NM][NM];
__device__ float g_prec[2][NB][NM];
__device__ float g_rw[2][NB][NR][NM];
__device__ float g_ww[2][NB][NM];
__device__ float g_usage[2][NB][NM];

// ---------------- converted (bf16 hi/lo split, fragment-swizzled) weights ----
// layout: [nfrag][k16][hl 2][lane 32][4 u32]  (one uint4 per (nfrag,k16,hl,lane))
__device__ unsigned g_W00[128 * 64 * 256];   // l0 cell0: 2048 x 1024
__device__ unsigned g_W01[128 * 69 * 256];   // l1 cell0: 2048 x 1104
__device__ unsigned g_W10[128 * 64 * 256];   // l0 cell1
__device__ unsigned g_W11[128 * 64 * 256];   // l1 cell1
__device__ unsigned g_Wif[2 * 12 * 32 * 256];// iface: 192(pad) x 512, per layer
__device__ unsigned g_Wo[32 * 37 * 256];     // out: 512 x 592
__device__ float g_bc[2 * 2 * 2048];         // gate-reordered biases [l][cell][n']

__device__ __forceinline__ float sigf(float x) { return 1.f / (1.f + expf(-x)); }
__device__ __forceinline__ float softplusf(float x) {
    return fmaxf(x, 0.f) + log1pf(expf(-fabsf(x)));
}
__device__ __forceinline__ float clipf(float x) {
    return fminf(fmaxf(x, -CLIPV), CLIPV);
}
// pack two floats as bf16x2: low half = a (k even), high half = b (k odd)
__device__ __forceinline__ uint32_t packbf(float a, float b) {
    uint32_t r;
    asm("cvt.rn.bf16x2.f32 %0, %1, %2;" : "=r"(r) : "f"(b), "f"(a));
    return r;
}
__device__ __forceinline__ float bfhi(float x) {
    return __bfloat162float(__float2bfloat16_rn(x));
}

// ---------------- init: zero all state --------------------------------------
__global__ void initk() {
    long i0 = blockIdx.x * (long)blockDim.x + threadIdx.x;
    long st = (long)gridDim.x * blockDim.x;
    for (long i = i0; i < 2L * 2 * 2 * NB * NH; i += st) ((float*)g_h)[i] = 0.f;
    for (long i = i0; i < 2L * 2 * NB * NH; i += st) ((float*)g_c)[i] = 0.f;
    for (long i = i0; i < (long)NB * NNIN; i += st) ((float*)g_inp)[i] = 0.f;
    for (long i = i0; i < 2L * NB * NM * NWC; i += st) ((float*)g_mem)[i] = 0.f;
    for (long i = i0; i < 2L * NB * NM * NM; i += st) ((float*)g_link)[i] = 0.f;
    for (long i = i0; i < 2L * NB * NM; i += st) {
        ((float*)g_prec)[i] = 0.f;
        ((float*)g_ww)[i] = 0.f;
        ((float*)g_usage)[i] = 0.f;
    }
    for (long i = i0; i < 2L * NB * NR * NM; i += st) ((float*)g_rw)[i] = 0.f;
}

// ---------------- weight conversion pre-pass (bf16 hi/lo) --------------------
// one thread per (nfrag, k16, lane); m16n8k16 A-fragment packing:
// reg0: (r0,        2c0+{0,1})   reg1: (r0+8,      2c0+{0,1})
// reg2: (r0,        2c0+8+{0,1}) reg3: (r0+8,      2c0+8+{0,1})
__global__ void prep(
    const float* __restrict__ W1, int ld1, int K1,
    const float* __restrict__ W2, int ld2, int K2,
    unsigned* __restrict__ dst, int gateReorder, int nReal, int nPad)
{
    const int K16 = (K1 + K2) >> 4;
    int idx = blockIdx.x * blockDim.x + threadIdx.x;
    int total = (nPad >> 4) * K16 * 32;
    if (idx >= total) return;
    int lane = idx & 31;
    int k16 = (idx >> 5) % K16;
    int nfrag = (idx >> 5) / K16;
    int r0 = lane >> 2, c0 = lane & 3;
    uint4 hi, lo;
    unsigned* ph = (unsigned*)&hi;
    unsigned* pl = (unsigned*)&lo;
#pragma unroll
    for (int reg = 0; reg < 4; ++reg) {
        int r = nfrag * 16 + r0 + 8 * (reg & 1);
        int kb = k16 * 16 + 2 * c0 + 8 * (reg >> 1);
        int row;
        if (gateReorder) { int j = r >> 2, g = r & 3; row = g * NH + j; }
        else row = r;
        float x0 = 0.f, x1 = 0.f;
        if (row < nReal) {
            x0 = (kb < K1) ? W1[(size_t)row * ld1 + kb]
                           : W2[(size_t)row * ld2 + (kb - K1)];
            x1 = (kb + 1 < K1) ? W1[(size_t)row * ld1 + kb + 1]
                               : W2[(size_t)row * ld2 + (kb + 1 - K1)];
        }
        float h0 = bfhi(x0), h1 = bfhi(x1);
        ph[reg] = packbf(h0, h1);
        pl[reg] = packbf(x0 - h0, x1 - h1);
    }
    ((uint4*)dst)[((size_t)(nfrag * K16 + k16) * 2 + 0) * 32 + lane] = hi;
    ((uint4*)dst)[((size_t)(nfrag * K16 + k16) * 2 + 1) * 32 + lane] = lo;
}

__global__ void prepbias(const float* bih0, const float* bhh0,
                         const float* bih1, const float* bhh1,
                         float* bc)
{
    int i = blockIdx.x * blockDim.x + threadIdx.x;
    if (i >= 2 * 2 * 2048) return;
    int n = i & 2047;
    int cell = (i >> 11) & 1;
    int l = i >> 12;
    int j = n >> 2, g = n & 3;
    const float* bi = cell ? bih1 : bih0;
    const float* bh = cell ? bhh1 : bhh0;
    bc[i] = bi[(size_t)l * 4 * NH + g * NH + j] + bh[(size_t)l * 4 * NH + g * NH + j];
}

// ---------------- compensated bf16 tensor-core GEMM --------------------------
// C[n', b] = W[n'] . concat(A1,A2)[b]  (block: 32 n' x 64 batch; 4 warps)
// 3-term split: Whi*Bhi + Wlo*Bhi + Whi*Blo
__device__ __forceinline__ void mma_bf16(float c[4], uint4 a, uint32_t b0, uint32_t b1) {
    asm volatile(
        "mma.sync.aligned.m16n8k16.row.col.f32.bf16.bf16.f32 "
        "{%0,%1,%2,%3}, {%4,%5,%6,%7}, {%8,%9}, {%0,%1,%2,%3};"
        : "+f"(c[0]), "+f"(c[1]), "+f"(c[2]), "+f"(c[3])
        : "r"(a.x), "r"(a.y), "r"(a.z), "r"(a.w), "r"(b0), "r"(b1));
}

__device__ __forceinline__ float4 ldA4(const float* __restrict__ A1, int sA1, int K1,
                                       const float* __restrict__ A2, int sA2,
                                       int b, int k)
{
    const float* p = (k < K1) ? A1 + (size_t)b * sA1 + k
                              : A2 + (size_t)b * sA2 + (k - K1);
    return *(const float4*)p;
}

template <int MODE>
__global__ __launch_bounds__(128) void tcgemm(
    const float* __restrict__ A1, int sA1, int K1,
    const float* __restrict__ A2, int sA2, int K2,
    const unsigned* __restrict__ Wswz,
    const float* __restrict__ bias,
    int nReal,
    float* __restrict__ cio,
    float* __restrict__ outp, int sOut,
    float* __restrict__ clipOut)
{
    __shared__ float sbuf[2112];   // staging: 2048 u32; epilogue: 32x66 f32
    uint32_t* shU = (uint32_t*)sbuf;
    const int K = K1 + K2;
    const int nch = K >> 4;        // k16 chunks
    const int tid = threadIdx.x;
    const int lane = tid & 31, warp = tid >> 5;
    const int wn = warp & 1, wb = warp >> 1;
    const int nblk = blockIdx.x;
    const int b0 = blockIdx.y * 64;

    float acc[4][4];
#pragma unroll
    for (int j = 0; j < 4; ++j)
#pragma unroll
        for (int q = 0; q < 4; ++q) acc[j][q] = 0.f;

    // W pointer: per (nfrag,k16): 64 uint4 (hi 32 + lo 32)
    const uint4* Wp = (const uint4*)Wswz + (size_t)(nblk * 2 + wn) * nch * 64 + lane;

    const int abl0 = tid >> 2;     // batch-local base 0..31
    const int akq = tid & 3;       // k quad within 16-chunk
    const int regl = akq >> 1;     // B-fragment reg this thread's pairs go to
    const int lnw = ((2 * akq) & 3);

    float4 arn[2];
    uint4 whi, wlo, whin, wlon;

    // staging store: for batch bl, pairs (k=4akq..+3) -> 2 consecutive u32
    auto stage = [&](int buf, float4 a, int bl) {
        float hx = bfhi(a.x), hy = bfhi(a.y), hz = bfhi(a.z), hw = bfhi(a.w);
        uint32_t hi0 = packbf(hx, hy), hi1 = packbf(hz, hw);
        uint32_t lo0 = packbf(a.x - hx, a.y - hy), lo1 = packbf(a.z - hz, a.w - hw);
        int bg = bl >> 3;
        int base = buf * 1024 + regl * 256 + bg * 32 + (bl & 7) * 4 + lnw;
        shU[base] = hi0;
        shU[base + 1] = hi1;
        shU[base + 512] = lo0;
        shU[base + 513] = lo1;
    };

    // prologue: chunk 0
    {
#pragma unroll
        for (int v = 0; v < 2; ++v) {
            float4 a = ldA4(A1, sA1, K1, A2, sA2, b0 + abl0 + v * 32, akq * 4);
            stage(0, a, abl0 + v * 32);
        }
        whi = Wp[0];
        wlo = Wp[32];
    }
    __syncthreads();

    for (int ch = 0; ch < nch; ++ch) {
        const int cur = ch & 1;
        if (ch + 1 < nch) {
#pragma unroll
            for (int v = 0; v < 2; ++v)
                arn[v] = ldA4(A1, sA1, K1, A2, sA2, b0 + abl0 + v * 32,
                              (ch + 1) * 16 + akq * 4);
            whin = Wp[(size_t)(ch + 1) * 64];
            wlon = Wp[(size_t)(ch + 1) * 64 + 32];
        }
#pragma unroll
        for (int j = 0; j < 4; ++j) {
            int bb8 = wb * 4 + j;
            int rb = cur * 1024 + bb8 * 32 + lane;
            uint32_t bhi0 = shU[rb];
            uint32_t bhi1 = shU[rb + 256];
            uint32_t blo0 = shU[rb + 512];
            uint32_t blo1 = shU[rb + 768];
            mma_bf16(acc[j], whi, bhi0, bhi1);
            mma_bf16(acc[j], wlo, bhi0, bhi1);
            mma_bf16(acc[j], whi, blo0, blo1);
        }
        if (ch + 1 < nch) {
            const int nxt = cur ^ 1;
#pragma unroll
            for (int v = 0; v < 2; ++v)
                stage(nxt, arn[v], abl0 + v * 32);
            whi = whin;
            wlo = wlon;
        }
        __syncthreads();
    }

    // ---- epilogue: transpose C fragments through shared ----
    const int CP = 66;
    {
        int r = lane >> 2;
        int cc = (lane & 3) * 2;
#pragma unroll
        for (int j = 0; j < 4; ++j) {
            int bl = wb * 32 + j * 8 + cc;
            int nl = wn * 16 + r;
            sbuf[nl * CP + bl] = acc[j][0];
            sbuf[nl * CP + bl + 1] = acc[j][1];
            sbuf[(nl + 8) * CP + bl] = acc[j][2];
            sbuf[(nl + 8) * CP + bl + 1] = acc[j][3];
        }
    }
    __syncthreads();

    if (MODE == 0) {
#pragma unroll
        for (int i = 0; i < 4; ++i) {
            int pair = i * 128 + tid;
            int j = pair & 7, bl = pair >> 3;
            int jg = nblk * 8 + j;
            int b = b0 + bl;
            float gi = sbuf[(j * 4 + 0) * CP + bl] + bias[nblk * 32 + j * 4 + 0];
            float gf = sbuf[(j * 4 + 1) * CP + bl] + bias[nblk * 32 + j * 4 + 1];
            float gg = sbuf[(j * 4 + 2) * CP + bl] + bias[nblk * 32 + j * 4 + 2];
            float go = sbuf[(j * 4 + 3) * CP + bl] + bias[nblk * 32 + j * 4 + 3];
            float cold = cio[(size_t)b * NH + jg];
            float cn = sigf(gf) * cold + sigf(gi) * tanhf(gg);
            float hn = sigf(go) * tanhf(cn);
            cio[(size_t)b * NH + jg] = cn;
            outp[(size_t)b * sOut + jg] = hn;
            if (clipOut) clipOut[(size_t)b * NNIN + jg] = clipf(hn);
        }
    } else {
#pragma unroll
        for (int i = 0; i < 16; ++i) {
            int pair = i * 128 + tid;
            int n = pair & 31, bl = pair >> 5;
            int ng = nblk * 32 + n;
            if (ng < nReal) {
                int b = b0 + bl;
                outp[(size_t)b * sOut + ng] = sbuf[n * CP + bl] + bias[ng];
            }
        }
    }
}

// ---------------- DNC memory step (iface precomputed) ------------------------
__global__ __launch_bounds__(128) void memstep(
    const float* __restrict__ ifcg,   // [NB][NIFP]
    float* __restrict__ memg, float* __restrict__ linkg,
    float* __restrict__ precg, float* __restrict__ rwg,
    float* __restrict__ wwg, float* __restrict__ usg,
    float* __restrict__ inp)
{
    const int RS = 80, WK = 84, WS = 104, ER = 105, WV = 125,
              FG = 145, AG = 149, WG = 150, RM = 151;
    const int b = blockIdx.x;
    const int tid = threadIdx.x;

    __shared__ float ifc[NIF];
    __shared__ float sm[NM * NWC];
    __shared__ float sl[NM * NM];
    __shared__ float sp[NM], srw[NR * NM], sww[NM], sus[NM];
    __shared__ float wcw[NM], alo[NM];
    __shared__ float rcw[NR * NM], fwd[NR * NM], bwd[NR * NM];

    for (int i = tid; i < NIF; i += 128) ifc[i] = ifcg[b * NIFP + i];
    for (int i = tid; i < NM * NWC; i += 128) sm[i] = memg[b * NM * NWC + i];
    for (int i = tid; i < NM * NM; i += 128) sl[i] = linkg[b * NM * NM + i];
    if (tid < NM) {
        sp[tid] = precg[b * NM + tid];
        sww[tid] = wwg[b * NM + tid];
        sus[tid] = usg[b * NM + tid];
    }
    if (tid >= 32 && tid < 32 + NR * NM) srw[tid - 32] = rwg[b * NR * NM + tid - 32];
    __syncthreads();

    // usage update (OLD ww, OLD rw)
    if (tid < NM) {
        int m = tid;
        float uu = sus[m] + (1.f - sus[m]) * sww[m];
        float psi = 1.f;
#pragma unroll
        for (int r = 0; r < NR; ++r)
            psi *= 1.f - sigf(ifc[FG + r]) * srw[r * NM + m];
        sus[m] = uu * psi;
    }
    __syncthreads();

    // write content weights (cosine on OLD memory)
    if (tid < NM) {
        int m = tid;
        float kn2 = 0.f, dot = 0.f, mn2 = 0.f;
#pragma unroll
        for (int w = 0; w < NWC; ++w) {
            float kv = tanhf(ifc[WK + w]);
            float mv = sm[m * NWC + w];
            kn2 = fmaf(kv, kv, kn2);
            mn2 = fmaf(mv, mv, mn2);
            dot = fmaf(kv, mv, dot);
        }
        wcw[m] = dot / ((sqrtf(kn2) + EPSF) * (sqrtf(mn2) + EPSF));
    }
    __syncthreads();
    if (tid == 0) {
        float str = softplusf(ifc[WS]);
        float mx = -1e30f;
        for (int m = 0; m < NM; ++m) { wcw[m] *= str; mx = fmaxf(mx, wcw[m]); }
        float s = 0.f;
        for (int m = 0; m < NM; ++m) { wcw[m] = expf(wcw[m] - mx); s += wcw[m]; }
        float inv = 1.f / s;
        for (int m = 0; m < NM; ++m) wcw[m] *= inv;
    }
    // allocation weights (stable ascending argsort of u)
    if (tid == 32) {
        float u[NM]; int idx[NM];
        for (int m = 0; m < NM; ++m) { u[m] = DELTAF + (1.f - DELTAF) * sus[m]; idx[m] = m; }
        for (int i = 1; i < NM; ++i) {
            float kv = u[i]; int ki = idx[i]; int j = i;
            while (j > 0 && u[j - 1] > kv) { u[j] = u[j - 1]; idx[j] = idx[j - 1]; --j; }
            u[j] = kv; idx[j] = ki;
        }
        float prod = 1.f;
        for (int j = 0; j < NM; ++j) { alo[idx[j]] = (1.f - u[j]) * prod; prod *= u[j]; }
    }
    __syncthreads();

    // new write weights
    if (tid < NM) {
        float ag = sigf(ifc[AG]), wg = sigf(ifc[WG]);
        sww[tid] = wg * (ag * alo[tid] + (1.f - ag) * wcw[tid]);
    }
    __syncthreads();

    // memory write
    for (int i = tid; i < NM * NWC; i += 128) {
        int m = i / NWC, w = i % NWC;
        float e = sigf(ifc[ER + w]);
        float v = tanhf(ifc[WV + w]);
        sm[i] = sm[i] * (1.f - sww[m] * e) + sww[m] * v;
    }
    __syncthreads();

    // link update (NEW ww, OLD prec)
    for (int i = tid; i < NM * NM; i += 128) {
        int ii = i >> 4, jj = i & 15;
        sl[i] = (ii == jj) ? 0.f
                           : (1.f - sww[ii] - sww[jj]) * sl[i] + sww[ii] * sp[jj];
    }
    __syncthreads();

    // precedence
    if (tid < NM) {
        float s = 0.f;
#pragma unroll
        for (int m = 0; m < NM; ++m) s += sww[m];
        sp[tid] = (1.f - s) * sp[tid] + sww[tid];
    }
    __syncthreads();

    // read content weights (cosine on NEW memory)
    if (tid < NR * NM) {
        int r = tid >> 4, m = tid & 15;
        float kn2 = 0.f, dot = 0.f, mn2 = 0.f;
#pragma unroll
        for (int w = 0; w < NWC; ++w) {
            float kv = tanhf(ifc[r * NWC + w]);
            float mv = sm[m * NWC + w];
            kn2 = fmaf(kv, kv, kn2);
            mn2 = fmaf(mv, mv, mn2);
            dot = fmaf(kv, mv, dot);
        }
        rcw[tid] = dot / ((sqrtf(kn2) + EPSF) * (sqrtf(mn2) + EPSF));
    }
    __syncthreads();
    if (tid < NR) {
        int r = tid;
        float str = softplusf(ifc[RS + r]);
        float mx = -1e30f;
        for (int m = 0; m < NM; ++m) { rcw[r * NM + m] *= str; mx = fmaxf(mx, rcw[r * NM + m]); }
        float s = 0.f;
        for (int m = 0; m < NM; ++m) { rcw[r * NM + m] = expf(rcw[r * NM + m] - mx); s += rcw[r * NM + m]; }
        float inv = 1.f / s;
        for (int m = 0; m < NM; ++m) rcw[r * NM + m] *= inv;
    }
    __syncthreads();

    // forward / backward (NEW link, OLD rw)
    if (tid < NR * NM) {
        int r = tid >> 4, q = tid & 15;
        float f = 0.f, bb = 0.f;
#pragma unroll
        for (int j = 0; j < NM; ++j) {
            f = fmaf(sl[q * NM + j], srw[r * NM + j], f);
            bb = fmaf(srw[r * NM + j], sl[j * NM + q], bb);
        }
        fwd[tid] = f;
        bwd[tid] = bb;
    }
    __syncthreads();

    // new read weights (mode softmax over 3)
    if (tid < NR * NM) {
        int r = tid >> 4;
        float e0 = ifc[RM + r * 3 + 0], e1 = ifc[RM + r * 3 + 1], e2 = ifc[RM + r * 3 + 2];
        float mx = fmaxf(e0, fmaxf(e1, e2));
        float x0 = expf(e0 - mx), x1 = expf(e1 - mx), x2 = expf(e2 - mx);
        float inv = 1.f / (x0 + x1 + x2);
        srw[tid] = (x0 * bwd[tid] + x1 * fwd[tid] + x2 * rcw[tid]) * inv;
    }
    __syncthreads();

    // read vectors -> g_inp[:, 512:592]
    if (tid < NRW) {
        int r = tid / NWC, w = tid % NWC;
        float s = 0.f;
#pragma unroll
        for (int m = 0; m < NM; ++m) s = fmaf(srw[r * NM + m], sm[m * NWC + w], s);
        inp[(size_t)b * NNIN + NIN + tid] = s;
    }

    // write back state
    for (int i = tid; i < NM * NWC; i += 128) memg[b * NM * NWC + i] = sm[i];
    for (int i = tid; i < NM * NM; i += 128) linkg[b * NM * NM + i] = sl[i];
    if (tid < NM) {
        precg[b * NM + tid] = sp[tid];
        wwg[b * NM + tid] = sww[tid];
        usg[b * NM + tid] = sus[tid];
    }
    if (tid >= 32 && tid < 32 + NR * NM) rwg[b * NR * NM + tid - 32] = srw[tid - 32];
}

// ---------------- host driver ------------------------------------------------
static inline int prepBlocks(int nPad, int K) {
    long total = (long)(nPad >> 4) * (K >> 4) * 32;
    return (int)((total + 255) / 256);
}

extern "C" void kernel_launch(void* const* d_in, const int* in_sizes, int n_in,
                              void* d_out, int out_size)
{
    const float* x      = (const float*)d_in[0];
    const float* W_ih0  = (const float*)d_in[1];
    const float* W_hh0  = (const float*)d_in[2];
    const float* b_ih0  = (const float*)d_in[3];
    const float* b_hh0  = (const float*)d_in[4];
    const float* W_ih1  = (const float*)d_in[5];
    const float* W_hh1  = (const float*)d_in[6];
    const float* b_ih1  = (const float*)d_in[7];
    const float* b_hh1  = (const float*)d_in[8];
    const float* W_if   = (const float*)d_in[9];
    const float* b_if   = (const float*)d_in[10];
    const float* W_out  = (const float*)d_in[11];
    const float* b_out  = (const float*)d_in[12];
    float* y = (float*)d_out;

    float *ph, *pc, *pinp, *pifc, *pmem, *plink, *pprec, *prw, *pww, *pus, *pbc;
    unsigned *pW00, *pW01, *pW10, *pW11, *pWif, *pWo;
    cudaGetSymbolAddress((void**)&ph,   g_h);
    cudaGetSymbolAddress((void**)&pc,   g_c);
    cudaGetSymbolAddress((void**)&pinp, g_inp);
    cudaGetSymbolAddress((void**)&pifc, g_ifc);
    cudaGetSymbolAddress((void**)&pmem, g_mem);
    cudaGetSymbolAddress((void**)&plink,g_link);
    cudaGetSymbolAddress((void**)&pprec,g_prec);
    cudaGetSymbolAddress((void**)&prw,  g_rw);
    cudaGetSymbolAddress((void**)&pww,  g_ww);
    cudaGetSymbolAddress((void**)&pus,  g_usage);
    cudaGetSymbolAddress((void**)&pW00, g_W00);
    cudaGetSymbolAddress((void**)&pW01, g_W01);
    cudaGetSymbolAddress((void**)&pW10, g_W10);
    cudaGetSymbolAddress((void**)&pW11, g_W11);
    cudaGetSymbolAddress((void**)&pWif, g_Wif);
    cudaGetSymbolAddress((void**)&pWo,  g_Wo);
    cudaGetSymbolAddress((void**)&pbc,  g_bc);

    auto hbuf = [&](int p, int l, int s) {
        return ph + (((size_t)p * 2 + l) * 2 + s) * NB * NH;
    };
    auto cbuf = [&](int l, int s) { return pc + ((size_t)l * 2 + s) * NB * NH; };

    initk<<<512, 256>>>();

    // ---- weight conversion pre-pass ----
    prep<<<prepBlocks(2048, 1024), 256>>>(W_ih0, NNIN, 512, W_hh0, NH, 512,
                                          pW00, 1, 2048, 2048);
    prep<<<prepBlocks(2048, 1104), 256>>>(W_ih0 + (size_t)4 * NH * NNIN, NNIN, 592,
                                          W_hh0 + (size_t)4 * NH * NH, NH, 512,
                                          pW01, 1, 2048, 2048);
    prep<<<prepBlocks(2048, 1024), 256>>>(W_ih1, NH, 512, W_hh1, NH, 512,
                                          pW10, 1, 2048, 2048);
    prep<<<prepBlocks(2048, 1024), 256>>>(W_ih1 + (size_t)4 * NH * NH, NH, 512,
                                          W_hh1 + (size_t)4 * NH * NH, NH, 512,
                                          pW11, 1, 2048, 2048);
    prep<<<prepBlocks(192, 512), 256>>>(W_if, NH, 512, W_if, NH, 0,
                                        pWif, 0, NIF, 192);
    prep<<<prepBlocks(192, 512), 256>>>(W_if + (size_t)NIF * NH, NH, 512,
                                        W_if + (size_t)NIF * NH, NH, 0,
                                        pWif + (size_t)12 * 32 * 256, 0, NIF, 192);
    prep<<<prepBlocks(512, 592), 256>>>(W_out, NNIN, 592, W_out, NNIN, 0,
                                        pWo, 0, 512, 512);
    prepbias<<<(2 * 2 * 2048 + 255) / 256, 256>>>(b_ih0, b_hh0, b_ih1, b_hh1, pbc);

    const unsigned* Wc0[2] = {pW00, pW01};
    const unsigned* Wc1[2] = {pW10, pW11};

    const dim3 gCell(64, 2);
    const dim3 gIf(6, 2);
    const dim3 gOut(16, 2);

    for (int t = 0; t < NT; ++t) {
        const int p = t & 1;
        for (int l = 0; l < 2; ++l) {
            // ---- cell 0 ----
            const float* A1; int sA1, K1;
            if (l == 0) { A1 = x + (size_t)t * NIN; sA1 = NT * NIN; K1 = NIN; }
            else        { A1 = pinp; sA1 = NNIN; K1 = NNIN; }
            tcgemm<0><<<gCell, 128>>>(
                A1, sA1, K1,
                hbuf(p, l, 0), NH, NH,
                Wc0[l],
                pbc + (size_t)(l * 2 + 0) * 2048,
                2048,
                cbuf(l, 0),
                hbuf(p ^ 1, l, 0), NH,
                nullptr);
            // ---- cell 1 ----
            tcgemm<0><<<gCell, 128>>>(
                hbuf(p ^ 1, l, 0), NH, NH,
                hbuf(p, l, 1), NH, NH,
                Wc1[l],
                pbc + (size_t)(l * 2 + 1) * 2048,
                2048,
                cbuf(l, 1),
                hbuf(p ^ 1, l, 1), NH,
                pinp);
            // ---- iface projection ----
            tcgemm<1><<<gIf, 128>>>(
                pinp, NNIN, 512,
                pinp, NNIN, 0,
                pWif + (size_t)l * 12 * 32 * 256,
                b_if + (size_t)l * NIF,
                NIF,
                nullptr,
                pifc, NIFP,
                nullptr);
            // ---- memory step ----
            memstep<<<NB, 128>>>(
                pifc,
                pmem + (size_t)l * NB * NM * NWC,
                plink + (size_t)l * NB * NM * NM,
                pprec + (size_t)l * NB * NM,
                prw + (size_t)l * NB * NR * NM,
                pww + (size_t)l * NB * NM,
                pus + (size_t)l * NB * NM,
                pinp);
        }
        // ---- output projection ----
        tcgemm<1><<<gOut, 128>>>(
            pinp, NNIN, 592,
            pinp, NNIN, 0,
            pWo,
            b_out,
            512,
            nullptr,
            y + (size_t)t * NIN, NT * NIN,
            nullptr);
    }
}

// round 7
// speedup vs baseline: 2.0372x; 1.2811x over previous
#include <cuda_runtime.h>
#include <cuda_bf16.h>
#include <math.h>
#include <stdint.h>

#define NB 128
#define NT 32
#define NIN 512
#define NH 512
#define NM 16
#define NWC 20
#define NR 4
#define NRW 80
#define NNIN 592
#define NIF 163
#define NIFP 192
#define CLIPV 20.0f
#define EPSF 1e-6f
#define DELTAF 5e-6f

// ---------------- persistent state (device globals; allocation-free) ----------
__device__ float g_h[2][2][2][NB][NH];   // [parity][layer][cell][b][h]
__device__ float g_c[2][2][NB][NH];      // [layer][cell][b][h]
__device__ float g_inp[NB][NNIN];        // concat(out, read_vecs)
__device__ float g_ifc[NB][NIFP];        // iface projection result
__device__ float g_xpart[NT * 2048 * NB];// precomputed x@Wih partial, [t][n'][b]
__device__ float g_mem[2][NB][NM][NWC];
__device__ float g_link[2][NB][NM][NM];
__device__ float g_prec[2][NB][NM];
__device__ float g_rw[2][NB][NR][NM];
__device__ float g_ww[2][NB][NM];
__device__ float g_usage[2][NB][NM];

// ---------------- converted (bf16 hi/lo split, fragment-swizzled) weights ----
// layout: [nfrag][k16][hl 2][lane 32][4 u32]
__device__ unsigned g_W00[128 * 64 * 256];   // l0 cell0: 2048 x (512x + 512h)
__device__ unsigned g_W01[128 * 69 * 256];   // l1 cell0: 2048 x 1104
__device__ unsigned g_W10[128 * 64 * 256];   // l0 cell1
__device__ unsigned g_W11[128 * 64 * 256];   // l1 cell1
__device__ unsigned g_Wif[2 * 12 * 32 * 256];// iface: 192(pad) x 512, per layer
__device__ unsigned g_Wo[32 * 37 * 256];     // out: 512 x 592
__device__ float g_bc[2 * 2 * 2048];         // gate-reordered biases [l][cell][n']

__device__ __forceinline__ float sigf(float x) { return 1.f / (1.f + expf(-x)); }
__device__ __forceinline__ float softplusf(float x) {
    return fmaxf(x, 0.f) + log1pf(expf(-fabsf(x)));
}
__device__ __forceinline__ float clipf(float x) {
    return fminf(fmaxf(x, -CLIPV), CLIPV);
}
__device__ __forceinline__ uint32_t packbf(float a, float b) {
    uint32_t r;
    asm("cvt.rn.bf16x2.f32 %0, %1, %2;" : "=r"(r) : "f"(b), "f"(a));
    return r;
}
__device__ __forceinline__ float bfhi(float x) {
    return __bfloat162float(__float2bfloat16_rn(x));
}

// ---------------- init: zero all state --------------------------------------
__global__ void initk() {
    long i0 = blockIdx.x * (long)blockDim.x + threadIdx.x;
    long st = (long)gridDim.x * blockDim.x;
    for (long i = i0; i < 2L * 2 * 2 * NB * NH; i += st) ((float*)g_h)[i] = 0.f;
    for (long i = i0; i < 2L * 2 * NB * NH; i += st) ((float*)g_c)[i] = 0.f;
    for (long i = i0; i < (long)NB * NNIN; i += st) ((float*)g_inp)[i] = 0.f;
    for (long i = i0; i < 2L * NB * NM * NWC; i += st) ((float*)g_mem)[i] = 0.f;
    for (long i = i0; i < 2L * NB * NM * NM; i += st) ((float*)g_link)[i] = 0.f;
    for (long i = i0; i < 2L * NB * NM; i += st) {
        ((float*)g_prec)[i] = 0.f;
        ((float*)g_ww)[i] = 0.f;
        ((float*)g_usage)[i] = 0.f;
    }
    for (long i = i0; i < 2L * NB * NR * NM; i += st) ((float*)g_rw)[i] = 0.f;
}

// ---------------- fused weight conversion pre-pass (7 jobs, bf16 hi/lo) ------
__global__ void prepAll(
    const float* __restrict__ W_ih0, const float* __restrict__ W_hh0,
    const float* __restrict__ W_ih1, const float* __restrict__ W_hh1,
    const float* __restrict__ W_if,  const float* __restrict__ W_out,
    unsigned* pW00, unsigned* pW01, unsigned* pW10, unsigned* pW11,
    unsigned* pWif, unsigned* pWo)
{
    const float *W1, *W2;
    int ld1, K1, ld2, K2, gr, nReal, nPad;
    unsigned* dst;
    switch (blockIdx.y) {
        case 0: W1 = W_ih0; ld1 = NNIN; K1 = 512; W2 = W_hh0; ld2 = NH; K2 = 512;
                dst = pW00; gr = 1; nReal = 2048; nPad = 2048; break;
        case 1: W1 = W_ih0 + (size_t)4 * NH * NNIN; ld1 = NNIN; K1 = 592;
                W2 = W_hh0 + (size_t)4 * NH * NH; ld2 = NH; K2 = 512;
                dst = pW01; gr = 1; nReal = 2048; nPad = 2048; break;
        case 2: W1 = W_ih1; ld1 = NH; K1 = 512; W2 = W_hh1; ld2 = NH; K2 = 512;
                dst = pW10; gr = 1; nReal = 2048; nPad = 2048; break;
        case 3: W1 = W_ih1 + (size_t)4 * NH * NH; ld1 = NH; K1 = 512;
                W2 = W_hh1 + (size_t)4 * NH * NH; ld2 = NH; K2 = 512;
                dst = pW11; gr = 1; nReal = 2048; nPad = 2048; break;
        case 4: W1 = W_if; ld1 = NH; K1 = 512; W2 = W_if; ld2 = NH; K2 = 0;
                dst = pWif; gr = 0; nReal = NIF; nPad = 192; break;
        case 5: W1 = W_if + (size_t)NIF * NH; ld1 = NH; K1 = 512;
                W2 = W1; ld2 = NH; K2 = 0;
                dst = pWif + (size_t)12 * 32 * 256; gr = 0; nReal = NIF; nPad = 192; break;
        default: W1 = W_out; ld1 = NNIN; K1 = 592; W2 = W_out; ld2 = NNIN; K2 = 0;
                dst = pWo; gr = 0; nReal = 512; nPad = 512; break;
    }
    const int K16 = (K1 + K2) >> 4;
    int idx = blockIdx.x * blockDim.x + threadIdx.x;
    int total = (nPad >> 4) * K16 * 32;
    if (idx >= total) return;
    int lane = idx & 31;
    int k16 = (idx >> 5) % K16;
    int nfrag = (idx >> 5) / K16;
    int r0 = lane >> 2, c0 = lane & 3;
    uint4 hi, lo;
    unsigned* ph = (unsigned*)&hi;
    unsigned* pl = (unsigned*)&lo;
#pragma unroll
    for (int reg = 0; reg < 4; ++reg) {
        int r = nfrag * 16 + r0 + 8 * (reg & 1);
        int kb = k16 * 16 + 2 * c0 + 8 * (reg >> 1);
        int row;
        if (gr) { int j = r >> 2, g = r & 3; row = g * NH + j; }
        else row = r;
        float x0 = 0.f, x1 = 0.f;
        if (row < nReal) {
            x0 = (kb < K1) ? W1[(size_t)row * ld1 + kb]
                           : W2[(size_t)row * ld2 + (kb - K1)];
            x1 = (kb + 1 < K1) ? W1[(size_t)row * ld1 + kb + 1]
                               : W2[(size_t)row * ld2 + (kb + 1 - K1)];
        }
        float h0 = bfhi(x0), h1 = bfhi(x1);
        ph[reg] = packbf(h0, h1);
        pl[reg] = packbf(x0 - h0, x1 - h1);
    }
    ((uint4*)dst)[((size_t)(nfrag * K16 + k16) * 2 + 0) * 32 + lane] = hi;
    ((uint4*)dst)[((size_t)(nfrag * K16 + k16) * 2 + 1) * 32 + lane] = lo;
}

__global__ void prepbias(const float* bih0, const float* bhh0,
                         const float* bih1, const float* bhh1, float* bc)
{
    int i = blockIdx.x * blockDim.x + threadIdx.x;
    if (i >= 2 * 2 * 2048) return;
    int n = i & 2047;
    int cell = (i >> 11) & 1;
    int l = i >> 12;
    int j = n >> 2, g = n & 3;
    const float* bi = cell ? bih1 : bih0;
    const float* bh = cell ? bhh1 : bhh0;
    bc[i] = bi[(size_t)l * 4 * NH + g * NH + j] + bh[(size_t)l * 4 * NH + g * NH + j];
}

// ---------------- compensated bf16 tensor-core GEMM --------------------------
// Tile: 32 n' x 32 batch, 128 threads (4 warps: wn = n16-half, wb = batch16-half)
// MODE 0: LSTM epilogue (+ optional precomputed partial `extra`, indexed [n'][b])
// MODE 1: linear + bias (nReal row guard)
// MODE 2: write raw acc to extra layout [t][n'][bidx]  (x-precompute)
__device__ __forceinline__ void mma_bf16(float c[4], uint4 a, uint32_t b0, uint32_t b1) {
    asm volatile(
        "mma.sync.aligned.m16n8k16.row.col.f32.bf16.bf16.f32 "
        "{%0,%1,%2,%3}, {%4,%5,%6,%7}, {%8,%9}, {%0,%1,%2,%3};"
        : "+f"(c[0]), "+f"(c[1]), "+f"(c[2]), "+f"(c[3])
        : "r"(a.x), "r"(a.y), "r"(a.z), "r"(a.w), "r"(b0), "r"(b1));
}

__device__ __forceinline__ float4 ldA4(const float* __restrict__ A1, int sA1, int K1,
                                       const float* __restrict__ A2, int sA2,
                                       int b, int k)
{
    const float* p = (k < K1) ? A1 + (size_t)b * sA1 + k
                              : A2 + (size_t)b * sA2 + (k - K1);
    return *(const float4*)p;
}

template <int MODE>
__global__ __launch_bounds__(128) void tcgemm(
    const float* __restrict__ A1, int sA1, int K1,
    const float* __restrict__ A2, int sA2, int K2,
    const unsigned* __restrict__ Wswz, int k16Stride, int chOff,
    const float* __restrict__ bias,
    int nReal,
    float* __restrict__ cio,
    float* __restrict__ outp, int sOut,
    float* __restrict__ clipOut,
    float* __restrict__ extra)
{
    __shared__ float sbuf[1152];   // staging: 1024 u32 (double-buffered); epi: 32x34
    uint32_t* shU = (uint32_t*)sbuf;
    const int K = K1 + K2;
    const int nch = K >> 4;
    const int tid = threadIdx.x;
    const int lane = tid & 31, warp = tid >> 5;
    const int wn = warp & 1, wb = warp >> 1;
    const int nblk = blockIdx.x;
    const int b0 = blockIdx.y * 32;

    float acc[2][4];
#pragma unroll
    for (int j = 0; j < 2; ++j)
#pragma unroll
        for (int q = 0; q < 4; ++q) acc[j][q] = 0.f;

    const uint4* Wp = (const uint4*)Wswz
        + ((size_t)(nblk * 2 + wn) * k16Stride + chOff) * 64 + lane;

    const int abl = tid >> 2;      // batch-local row 0..31
    const int akq = tid & 3;       // k quad within 16-chunk
    const int regl = akq >> 1;
    const int lnw = (2 * akq) & 3;

    float4 arn;
    uint4 whi, wlo, whin, wlon;

    auto stage = [&](int buf, float4 a) {
        float hx = bfhi(a.x), hy = bfhi(a.y), hz = bfhi(a.z), hw = bfhi(a.w);
        int base = buf * 512 + regl * 128 + (abl >> 3) * 32 + (abl & 7) * 4 + lnw;
        shU[base] = packbf(hx, hy);
        shU[base + 1] = packbf(hz, hw);
        shU[base + 256] = packbf(a.x - hx, a.y - hy);
        shU[base + 257] = packbf(a.z - hz, a.w - hw);
    };

    // prologue: chunk 0
    stage(0, ldA4(A1, sA1, K1, A2, sA2, b0 + abl, akq * 4));
    whi = Wp[0];
    wlo = Wp[32];
    __syncthreads();

    for (int ch = 0; ch < nch; ++ch) {
        const int cur = ch & 1;
        if (ch + 1 < nch) {
            arn = ldA4(A1, sA1, K1, A2, sA2, b0 + abl, (ch + 1) * 16 + akq * 4);
            whin = Wp[(size_t)(ch + 1) * 64];
            wlon = Wp[(size_t)(ch + 1) * 64 + 32];
        }
#pragma unroll
        for (int j = 0; j < 2; ++j) {
            int bb8 = wb * 2 + j;
            int rb = cur * 512 + bb8 * 32 + lane;
            uint32_t bhi0 = shU[rb];
            uint32_t bhi1 = shU[rb + 128];
            uint32_t blo0 = shU[rb + 256];
            uint32_t blo1 = shU[rb + 384];
            mma_bf16(acc[j], whi, bhi0, bhi1);
            mma_bf16(acc[j], wlo, bhi0, bhi1);
            mma_bf16(acc[j], whi, blo0, blo1);
        }
        if (ch + 1 < nch) {
            stage(cur ^ 1, arn);
            whi = whin;
            wlo = wlon;
        }
        __syncthreads();
    }

    // ---- epilogue: transpose C fragments through shared ----
    const int CP = 34;
    {
        int r = lane >> 2;
        int cc = (lane & 3) * 2;
#pragma unroll
        for (int j = 0; j < 2; ++j) {
            int bl = wb * 16 + j * 8 + cc;
            int nl = wn * 16 + r;
            sbuf[nl * CP + bl] = acc[j][0];
            sbuf[nl * CP + bl + 1] = acc[j][1];
            sbuf[(nl + 8) * CP + bl] = acc[j][2];
            sbuf[(nl + 8) * CP + bl + 1] = acc[j][3];
        }
    }
    __syncthreads();

    if (MODE == 0) {
#pragma unroll
        for (int i = 0; i < 2; ++i) {
            int pair = i * 128 + tid;
            int j = pair & 7, bl = pair >> 3;
            int jg = nblk * 8 + j;
            int b = b0 + bl;
            float e0 = 0.f, e1 = 0.f, e2 = 0.f, e3 = 0.f;
            if (extra) {
                const float* ep = extra + (size_t)(nblk * 32 + j * 4) * NB + b;
                e0 = ep[0]; e1 = ep[NB]; e2 = ep[2 * NB]; e3 = ep[3 * NB];
            }
            float gi = sbuf[(j * 4 + 0) * CP + bl] + bias[nblk * 32 + j * 4 + 0] + e0;
            float gf = sbuf[(j * 4 + 1) * CP + bl] + bias[nblk * 32 + j * 4 + 1] + e1;
            float gg = sbuf[(j * 4 + 2) * CP + bl] + bias[nblk * 32 + j * 4 + 2] + e2;
            float go = sbuf[(j * 4 + 3) * CP + bl] + bias[nblk * 32 + j * 4 + 3] + e3;
            float cold = cio[(size_t)b * NH + jg];
            float cn = sigf(gf) * cold + sigf(gi) * tanhf(gg);
            float hn = sigf(go) * tanhf(cn);
            cio[(size_t)b * NH + jg] = cn;
            outp[(size_t)b * sOut + jg] = hn;
            if (clipOut) clipOut[(size_t)b * NNIN + jg] = clipf(hn);
        }
    } else if (MODE == 1) {
#pragma unroll
        for (int i = 0; i < 8; ++i) {
            int pair = i * 128 + tid;
            int n = pair & 31, bl = pair >> 5;
            int ng = nblk * 32 + n;
            if (ng < nReal) {
                int b = b0 + bl;
                outp[(size_t)b * sOut + ng] = sbuf[n * CP + bl] + bias[ng];
            }
        }
    } else {
        // MODE 2: x-precompute, batch index bg = b*NT + t -> [t][n'][b]
#pragma unroll
        for (int i = 0; i < 8; ++i) {
            int pair = i * 128 + tid;
            int n = pair & 31, bl = pair >> 5;
            int ng = nblk * 32 + n;
            int bg = b0 + bl;
            int t = bg & (NT - 1);
            int bi = bg >> 5;
            outp[((size_t)t * 2048 + ng) * NB + bi] = sbuf[n * CP + bl];
        }
    }
}

// ---------------- DNC memory step (iface precomputed) ------------------------
__global__ __launch_bounds__(128) void memstep(
    const float* __restrict__ ifcg,
    float* __restrict__ memg, float* __restrict__ linkg,
    float* __restrict__ precg, float* __restrict__ rwg,
    float* __restrict__ wwg, float* __restrict__ usg,
    float* __restrict__ inp)
{
    const int RS = 80, WK = 84, WS = 104, ER = 105, WV = 125,
              FG = 145, AG = 149, WG = 150, RM = 151;
    const int b = blockIdx.x;
    const int tid = threadIdx.x;

    __shared__ float ifc[NIF];
    __shared__ float sm[NM * NWC];
    __shared__ float sl[NM * NM];
    __shared__ float sp[NM], srw[NR * NM], sww[NM], sus[NM];
    __shared__ float wcw[NM], alo[NM];
    __shared__ float rcw[NR * NM], fwd[NR * NM], bwd[NR * NM];

    for (int i = tid; i < NIF; i += 128) ifc[i] = ifcg[b * NIFP + i];
    for (int i = tid; i < NM * NWC; i += 128) sm[i] = memg[b * NM * NWC + i];
    for (int i = tid; i < NM * NM; i += 128) sl[i] = linkg[b * NM * NM + i];
    if (tid < NM) {
        sp[tid] = precg[b * NM + tid];
        sww[tid] = wwg[b * NM + tid];
        sus[tid] = usg[b * NM + tid];
    }
    if (tid >= 32 && tid < 32 + NR * NM) srw[tid - 32] = rwg[b * NR * NM + tid - 32];
    __syncthreads();

    if (tid < NM) {
        int m = tid;
        float uu = sus[m] + (1.f - sus[m]) * sww[m];
        float psi = 1.f;
#pragma unroll
        for (int r = 0; r < NR; ++r)
            psi *= 1.f - sigf(ifc[FG + r]) * srw[r * NM + m];
        sus[m] = uu * psi;
    }
    __syncthreads();

    if (tid < NM) {
        int m = tid;
        float kn2 = 0.f, dot = 0.f, mn2 = 0.f;
#pragma unroll
        for (int w = 0; w < NWC; ++w) {
            float kv = tanhf(ifc[WK + w]);
            float mv = sm[m * NWC + w];
            kn2 = fmaf(kv, kv, kn2);
            mn2 = fmaf(mv, mv, mn2);
            dot = fmaf(kv, mv, dot);
        }
        wcw[m] = dot / ((sqrtf(kn2) + EPSF) * (sqrtf(mn2) + EPSF));
    }
    __syncthreads();
    if (tid == 0) {
        float str = softplusf(ifc[WS]);
        float mx = -1e30f;
        for (int m = 0; m < NM; ++m) { wcw[m] *= str; mx = fmaxf(mx, wcw[m]); }
        float s = 0.f;
        for (int m = 0; m < NM; ++m) { wcw[m] = expf(wcw[m] - mx); s += wcw[m]; }
        float inv = 1.f / s;
        for (int m = 0; m < NM; ++m) wcw[m] *= inv;
    }
    if (tid == 32) {
        float u[NM]; int idx[NM];
        for (int m = 0; m < NM; ++m) { u[m] = DELTAF + (1.f - DELTAF) * sus[m]; idx[m] = m; }
        for (int i = 1; i < NM; ++i) {
            float kv = u[i]; int ki = idx[i]; int j = i;
            while (j > 0 && u[j - 1] > kv) { u[j] = u[j - 1]; idx[j] = idx[j - 1]; --j; }
            u[j] = kv; idx[j] = ki;
        }
        float prod = 1.f;
        for (int j = 0; j < NM; ++j) { alo[idx[j]] = (1.f - u[j]) * prod; prod *= u[j]; }
    }
    __syncthreads();

    if (tid < NM) {
        float ag = sigf(ifc[AG]), wg = sigf(ifc[WG]);
        sww[tid] = wg * (ag * alo[tid] + (1.f - ag) * wcw[tid]);
    }
    __syncthreads();

    for (int i = tid; i < NM * NWC; i += 128) {
        int m = i / NWC, w = i % NWC;
        float e = sigf(ifc[ER + w]);
        float v = tanhf(ifc[WV + w]);
        sm[i] = sm[i] * (1.f - sww[m] * e) + sww[m] * v;
    }
    __syncthreads();

    for (int i = tid; i < NM * NM; i += 128) {
        int ii = i >> 4, jj = i & 15;
        sl[i] = (ii == jj) ? 0.f
                           : (1.f - sww[ii] - sww[jj]) * sl[i] + sww[ii] * sp[jj];
    }
    __syncthreads();

    if (tid < NM) {
        float s = 0.f;
#pragma unroll
        for (int m = 0; m < NM; ++m) s += sww[m];
        sp[tid] = (1.f - s) * sp[tid] + sww[tid];
    }
    __syncthreads();

    if (tid < NR * NM) {
        int r = tid >> 4, m = tid & 15;
        float kn2 = 0.f, dot = 0.f, mn2 = 0.f;
#pragma unroll
        for (int w = 0; w < NWC; ++w) {
            float kv = tanhf(ifc[r * NWC + w]);
            float mv = sm[m * NWC + w];
            kn2 = fmaf(kv, kv, kn2);
            mn2 = fmaf(mv, mv, mn2);
            dot = fmaf(kv, mv, dot);
        }
        rcw[tid] = dot / ((sqrtf(kn2) + EPSF) * (sqrtf(mn2) + EPSF));
    }
    __syncthreads();
    if (tid < NR) {
        int r = tid;
        float str = softplusf(ifc[RS + r]);
        float mx = -1e30f;
        for (int m = 0; m < NM; ++m) { rcw[r * NM + m] *= str; mx = fmaxf(mx, rcw[r * NM + m]); }
        float s = 0.f;
        for (int m = 0; m < NM; ++m) { rcw[r * NM + m] = expf(rcw[r * NM + m] - mx); s += rcw[r * NM + m]; }
        float inv = 1.f / s;
        for (int m = 0; m < NM; ++m) rcw[r * NM + m] *= inv;
    }
    __syncthreads();

    if (tid < NR * NM) {
        int r = tid >> 4, q = tid & 15;
        float f = 0.f, bb = 0.f;
#pragma unroll
        for (int j = 0; j < NM; ++j) {
            f = fmaf(sl[q * NM + j], srw[r * NM + j], f);
            bb = fmaf(srw[r * NM + j], sl[j * NM + q], bb);
        }
        fwd[tid] = f;
        bwd[tid] = bb;
    }
    __syncthreads();

    if (tid < NR * NM) {
        int r = tid >> 4;
        float e0 = ifc[RM + r * 3 + 0], e1 = ifc[RM + r * 3 + 1], e2 = ifc[RM + r * 3 + 2];
        float mx = fmaxf(e0, fmaxf(e1, e2));
        float x0 = expf(e0 - mx), x1 = expf(e1 - mx), x2 = expf(e2 - mx);
        float inv = 1.f / (x0 + x1 + x2);
        srw[tid] = (x0 * bwd[tid] + x1 * fwd[tid] + x2 * rcw[tid]) * inv;
    }
    __syncthreads();

    if (tid < NRW) {
        int r = tid / NWC, w = tid % NWC;
        float s = 0.f;
#pragma unroll
        for (int m = 0; m < NM; ++m) s = fmaf(srw[r * NM + m], sm[m * NWC + w], s);
        inp[(size_t)b * NNIN + NIN + tid] = s;
    }

    for (int i = tid; i < NM * NWC; i += 128) memg[b * NM * NWC + i] = sm[i];
    for (int i = tid; i < NM * NM; i += 128) linkg[b * NM * NM + i] = sl[i];
    if (tid < NM) {
        precg[b * NM + tid] = sp[tid];
        wwg[b * NM + tid] = sww[tid];
        usg[b * NM + tid] = sus[tid];
    }
    if (tid >= 32 && tid < 32 + NR * NM) rwg[b * NR * NM + tid - 32] = srw[tid - 32];
}

// ---------------- host driver ------------------------------------------------
extern "C" void kernel_launch(void* const* d_in, const int* in_sizes, int n_in,
                              void* d_out, int out_size)
{
    const float* x      = (const float*)d_in[0];
    const float* W_ih0  = (const float*)d_in[1];
    const float* W_hh0  = (const float*)d_in[2];
    const float* b_ih0  = (const float*)d_in[3];
    const float* b_hh0  = (const float*)d_in[4];
    const float* W_ih1  = (const float*)d_in[5];
    const float* W_hh1  = (const float*)d_in[6];
    const float* b_ih1  = (const float*)d_in[7];
    const float* b_hh1  = (const float*)d_in[8];
    const float* W_if   = (const float*)d_in[9];
    const float* b_if   = (const float*)d_in[10];
    const float* W_out  = (const float*)d_in[11];
    const float* b_out  = (const float*)d_in[12];
    float* y = (float*)d_out;

    float *ph, *pc, *pinp, *pifc, *pxp, *pmem, *plink, *pprec, *prw, *pww, *pus, *pbc;
    unsigned *pW00, *pW01, *pW10, *pW11, *pWif, *pWo;
    cudaGetSymbolAddress((void**)&ph,   g_h);
    cudaGetSymbolAddress((void**)&pc,   g_c);
    cudaGetSymbolAddress((void**)&pinp, g_inp);
    cudaGetSymbolAddress((void**)&pifc, g_ifc);
    cudaGetSymbolAddress((void**)&pxp,  g_xpart);
    cudaGetSymbolAddress((void**)&pmem, g_mem);
    cudaGetSymbolAddress((void**)&plink,g_link);
    cudaGetSymbolAddress((void**)&pprec,g_prec);
    cudaGetSymbolAddress((void**)&prw,  g_rw);
    cudaGetSymbolAddress((void**)&pww,  g_ww);
    cudaGetSymbolAddress((void**)&pus,  g_usage);
    cudaGetSymbolAddress((void**)&pW00, g_W00);
    cudaGetSymbolAddress((void**)&pW01, g_W01);
    cudaGetSymbolAddress((void**)&pW10, g_W10);
    cudaGetSymbolAddress((void**)&pW11, g_W11);
    cudaGetSymbolAddress((void**)&pWif, g_Wif);
    cudaGetSymbolAddress((void**)&pWo,  g_Wo);
    cudaGetSymbolAddress((void**)&pbc,  g_bc);

    auto hbuf = [&](int p, int l, int s) {
        return ph + (((size_t)p * 2 + l) * 2 + s) * NB * NH;
    };
    auto cbuf = [&](int l, int s) { return pc + ((size_t)l * 2 + s) * NB * NH; };

    // launch order matters for ncu -s 5 -c 1: #5 = cell1-l0 tcgemm
    initk<<<512, 256>>>();                                               // 0
    prepAll<<<dim3(1104, 7), 256>>>(W_ih0, W_hh0, W_ih1, W_hh1, W_if,    // 1
                                    W_out, pW00, pW01, pW10, pW11, pWif, pWo);
    prepbias<<<(2 * 2 * 2048 + 255) / 256, 256>>>(b_ih0, b_hh0,          // 2
                                                  b_ih1, b_hh1, pbc);
    // x-precompute: batch 4096 = b*NT + t, K=512, chunks 0..31 of W00
    tcgemm<2><<<dim3(64, 128), 128>>>(x, NIN, 512, x, NIN, 0,            // 3
                                      pW00, 64, 0, nullptr, 2048,
                                      nullptr, pxp, 0, nullptr, nullptr);

    const unsigned* Wc1[2] = {pW10, pW11};
    const dim3 gCell(64, 4);
    const dim3 gIf(6, 4);
    const dim3 gOut(16, 4);

    for (int t = 0; t < NT; ++t) {
        const int p = t & 1;
        for (int l = 0; l < 2; ++l) {
            // ---- cell 0 ----
            if (l == 0) {
                // K=512 (hidden only) + precomputed x-partial
                tcgemm<0><<<gCell, 128>>>(
                    hbuf(p, 0, 0), NH, 512, hbuf(p, 0, 0), NH, 0,
                    pW00, 64, 32,
                    pbc, 2048,
                    cbuf(0, 0),
                    hbuf(p ^ 1, 0, 0), NH,
                    nullptr,
                    pxp + (size_t)t * 2048 * NB);
            } else {
                tcgemm<0><<<gCell, 128>>>(
                    pinp, NNIN, 592, hbuf(p, 1, 0), NH, 512,
                    pW01, 69, 0,
                    pbc + (size_t)2 * 2048, 2048,
                    cbuf(1, 0),
                    hbuf(p ^ 1, 1, 0), NH,
                    nullptr, nullptr);
            }
            // ---- cell 1 ----
            tcgemm<0><<<gCell, 128>>>(
                hbuf(p ^ 1, l, 0), NH, 512, hbuf(p, l, 1), NH, 512,
                Wc1[l], 64, 0,
                pbc + (size_t)(l * 2 + 1) * 2048, 2048,
                cbuf(l, 1),
                hbuf(p ^ 1, l, 1), NH,
                pinp, nullptr);
            // ---- iface projection ----
            tcgemm<1><<<gIf, 128>>>(
                pinp, NNIN, 512, pinp, NNIN, 0,
                pWif + (size_t)l * 12 * 32 * 256, 32, 0,
                b_if + (size_t)l * NIF, NIF,
                nullptr, pifc, NIFP, nullptr, nullptr);
            // ---- memory step ----
            memstep<<<NB, 128>>>(
                pifc,
                pmem + (size_t)l * NB * NM * NWC,
                plink + (size_t)l * NB * NM * NM,
                pprec + (size_t)l * NB * NM,
                prw + (size_t)l * NB * NR * NM,
                pww + (size_t)l * NB * NM,
                pus + (size_t)l * NB * NM,
                pinp);
        }
        // ---- output projection ----
        tcgemm<1><<<gOut, 128>>>(
            pinp, NNIN, 592, pinp, NNIN, 0,
            pWo, 37, 0,
            b_out, 512,
            nullptr, y + (size_t)t * NIN, NT * NIN, nullptr, nullptr);
    }
}

// round 8
// speedup vs baseline: 2.6296x; 1.2908x over previous
#include <cuda_runtime.h>
#include <cuda_bf16.h>
#include <math.h>
#include <stdint.h>

#define NB 128
#define NT 32
#define NIN 512
#define NH 512
#define NM 16
#define NWC 20
#define NR 4
#define NRW 80
#define NNIN 592
#define NIF 163
#define NIFP 192
#define CLIPV 20.0f
#define EPSF 1e-6f
#define DELTAF 5e-6f

// ---------------- persistent state (device globals; allocation-free) ----------
__device__ float g_h[2][2][2][NB][NH];   // [parity][layer][cell][b][h]
__device__ float g_c[2][2][NB][NH];      // [layer][cell][b][h]
__device__ float g_inp[NB][NNIN];        // concat(out, read_vecs)
__device__ float g_ifc[NB][NIFP];        // iface projection result
__device__ float g_xpart[NT * 2048 * NB];// precomputed x@Wih partial, [t][n'][b]
__device__ float g_mem[2][NB][NM][NWC];
__device__ float g_link[2][NB][NM][NM];
__device__ float g_prec[2][NB][NM];
__device__ float g_rw[2][NB][NR][NM];
__device__ float g_ww[2][NB][NM];
__device__ float g_usage[2][NB][NM];

// ---------------- converted (bf16 hi/lo split, fragment-swizzled) weights ----
// layout: [nfrag][k16][hl 2][lane 32][4 u32]
__device__ unsigned g_W00[128 * 64 * 256];   // l0 cell0: 2048 x (512x + 512h)
__device__ unsigned g_W01[128 * 69 * 256];   // l1 cell0: 2048 x 1104
__device__ unsigned g_W10[128 * 64 * 256];   // l0 cell1
__device__ unsigned g_W11[128 * 64 * 256];   // l1 cell1
__device__ unsigned g_Wif[2 * 12 * 32 * 256];// iface: 192(pad) x 512, per layer
__device__ unsigned g_Wo[32 * 37 * 256];     // out: 512 x 592
__device__ float g_bc[2 * 2 * 2048];         // gate-reordered biases [l][cell][n']

__device__ __forceinline__ float sigf(float x) { return 1.f / (1.f + expf(-x)); }
__device__ __forceinline__ float softplusf(float x) {
    return fmaxf(x, 0.f) + log1pf(expf(-fabsf(x)));
}
__device__ __forceinline__ float clipf(float x) {
    return fminf(fmaxf(x, -CLIPV), CLIPV);
}
__device__ __forceinline__ uint32_t packbf(float a, float b) {
    uint32_t r;
    asm("cvt.rn.bf16x2.f32 %0, %1, %2;" : "=r"(r) : "f"(b), "f"(a));
    return r;
}
__device__ __forceinline__ float bfhi(float x) {
    return __bfloat162float(__float2bfloat16_rn(x));
}
// split (x,y) -> bf16x2 hi + bf16x2 lo residual, all in registers
__device__ __forceinline__ void cvt_hilo(float x, float y, uint32_t& hi, uint32_t& lo) {
    uint32_t h = packbf(x, y);
    float hx = __uint_as_float(h << 16);
    float hy = __uint_as_float(h & 0xffff0000u);
    lo = packbf(x - hx, y - hy);
    hi = h;
}

// ---------------- init: zero all state --------------------------------------
__global__ void initk() {
    long i0 = blockIdx.x * (long)blockDim.x + threadIdx.x;
    long st = (long)gridDim.x * blockDim.x;
    for (long i = i0; i < 2L * 2 * 2 * NB * NH; i += st) ((float*)g_h)[i] = 0.f;
    for (long i = i0; i < 2L * 2 * NB * NH; i += st) ((float*)g_c)[i] = 0.f;
    for (long i = i0; i < (long)NB * NNIN; i += st) ((float*)g_inp)[i] = 0.f;
    for (long i = i0; i < 2L * NB * NM * NWC; i += st) ((float*)g_mem)[i] = 0.f;
    for (long i = i0; i < 2L * NB * NM * NM; i += st) ((float*)g_link)[i] = 0.f;
    for (long i = i0; i < 2L * NB * NM; i += st) {
        ((float*)g_prec)[i] = 0.f;
        ((float*)g_ww)[i] = 0.f;
        ((float*)g_usage)[i] = 0.f;
    }
    for (long i = i0; i < 2L * NB * NR * NM; i += st) ((float*)g_rw)[i] = 0.f;
}

// ---------------- fused weight conversion pre-pass (7 jobs, bf16 hi/lo) ------
__global__ void prepAll(
    const float* __restrict__ W_ih0, const float* __restrict__ W_hh0,
    const float* __restrict__ W_ih1, const float* __restrict__ W_hh1,
    const float* __restrict__ W_if,  const float* __restrict__ W_out,
    unsigned* pW00, unsigned* pW01, unsigned* pW10, unsigned* pW11,
    unsigned* pWif, unsigned* pWo)
{
    const float *W1, *W2;
    int ld1, K1, ld2, K2, gr, nReal, nPad;
    unsigned* dst;
    switch (blockIdx.y) {
        case 0: W1 = W_ih0; ld1 = NNIN; K1 = 512; W2 = W_hh0; ld2 = NH; K2 = 512;
                dst = pW00; gr = 1; nReal = 2048; nPad = 2048; break;
        case 1: W1 = W_ih0 + (size_t)4 * NH * NNIN; ld1 = NNIN; K1 = 592;
                W2 = W_hh0 + (size_t)4 * NH * NH; ld2 = NH; K2 = 512;
                dst = pW01; gr = 1; nReal = 2048; nPad = 2048; break;
        case 2: W1 = W_ih1; ld1 = NH; K1 = 512; W2 = W_hh1; ld2 = NH; K2 = 512;
                dst = pW10; gr = 1; nReal = 2048; nPad = 2048; break;
        case 3: W1 = W_ih1 + (size_t)4 * NH * NH; ld1 = NH; K1 = 512;
                W2 = W_hh1 + (size_t)4 * NH * NH; ld2 = NH; K2 = 512;
                dst = pW11; gr = 1; nReal = 2048; nPad = 2048; break;
        case 4: W1 = W_if; ld1 = NH; K1 = 512; W2 = W_if; ld2 = NH; K2 = 0;
                dst = pWif; gr = 0; nReal = NIF; nPad = 192; break;
        case 5: W1 = W_if + (size_t)NIF * NH; ld1 = NH; K1 = 512;
                W2 = W1; ld2 = NH; K2 = 0;
                dst = pWif + (size_t)12 * 32 * 256; gr = 0; nReal = NIF; nPad = 192; break;
        default: W1 = W_out; ld1 = NNIN; K1 = 592; W2 = W_out; ld2 = NNIN; K2 = 0;
                dst = pWo; gr = 0; nReal = 512; nPad = 512; break;
    }
    const int K16 = (K1 + K2) >> 4;
    int idx = blockIdx.x * blockDim.x + threadIdx.x;
    int total = (nPad >> 4) * K16 * 32;
    if (idx >= total) return;
    int lane = idx & 31;
    int k16 = (idx >> 5) % K16;
    int nfrag = (idx >> 5) / K16;
    int r0 = lane >> 2, c0 = lane & 3;
    uint4 hi, lo;
    unsigned* ph = (unsigned*)&hi;
    unsigned* pl = (unsigned*)&lo;
#pragma unroll
    for (int reg = 0; reg < 4; ++reg) {
        int r = nfrag * 16 + r0 + 8 * (reg & 1);
        int kb = k16 * 16 + 2 * c0 + 8 * (reg >> 1);
        int row;
        if (gr) { int j = r >> 2, g = r & 3; row = g * NH + j; }
        else row = r;
        float x0 = 0.f, x1 = 0.f;
        if (row < nReal) {
            x0 = (kb < K1) ? W1[(size_t)row * ld1 + kb]
                           : W2[(size_t)row * ld2 + (kb - K1)];
            x1 = (kb + 1 < K1) ? W1[(size_t)row * ld1 + kb + 1]
                               : W2[(size_t)row * ld2 + (kb + 1 - K1)];
        }
        float h0 = bfhi(x0), h1 = bfhi(x1);
        ph[reg] = packbf(h0, h1);
        pl[reg] = packbf(x0 - h0, x1 - h1);
    }
    ((uint4*)dst)[((size_t)(nfrag * K16 + k16) * 2 + 0) * 32 + lane] = hi;
    ((uint4*)dst)[((size_t)(nfrag * K16 + k16) * 2 + 1) * 32 + lane] = lo;
}

__global__ void prepbias(const float* bih0, const float* bhh0,
                         const float* bih1, const float* bhh1, float* bc)
{
    int i = blockIdx.x * blockDim.x + threadIdx.x;
    if (i >= 2 * 2 * 2048) return;
    int n = i & 2047;
    int cell = (i >> 11) & 1;
    int l = i >> 12;
    int j = n >> 2, g = n & 3;
    const float* bi = cell ? bih1 : bih0;
    const float* bh = cell ? bhh1 : bhh0;
    bc[i] = bi[(size_t)l * 4 * NH + g * NH + j] + bh[(size_t)l * 4 * NH + g * NH + j];
}

// ---------------- compensated bf16 tensor-core GEMM (register-direct B) ------
// Tile: 32 n' x 16 batch, 128 threads = 4 independent warps
//   warp (wn, wb): rows n' in [nblk*32 + wn*16, +16), batch cols [b0 + wb*8, +8)
// B fragment built straight from global via 2x float2 per lane per chunk; no
// shared staging, no mainloop __syncthreads. 3-term hi/lo compensation.
__device__ __forceinline__ void mma_bf16(float c[4], uint4 a, uint32_t b0, uint32_t b1) {
    asm volatile(
        "mma.sync.aligned.m16n8k16.row.col.f32.bf16.bf16.f32 "
        "{%0,%1,%2,%3}, {%4,%5,%6,%7}, {%8,%9}, {%0,%1,%2,%3};"
        : "+f"(c[0]), "+f"(c[1]), "+f"(c[2]), "+f"(c[3])
        : "r"(a.x), "r"(a.y), "r"(a.z), "r"(a.w), "r"(b0), "r"(b1));
}

template <int MODE>
__global__ __launch_bounds__(128, 8) void tcgemm(
    const float* __restrict__ A1, int sA1, int K1,
    const float* __restrict__ A2, int sA2, int K2,
    const unsigned* __restrict__ Wswz, int k16Stride, int chOff,
    const float* __restrict__ bias,
    int nReal,
    float* __restrict__ cio,
    float* __restrict__ outp, int sOut,
    float* __restrict__ clipOut,
    float* __restrict__ extra)
{
    __shared__ float sbuf[32 * 18];
    const int K = K1 + K2;
    const int nch = K >> 4;
    const int tid = threadIdx.x;
    const int lane = tid & 31, warp = tid >> 5;
    const int wn = warp & 1, wb = warp >> 1;
    const int nblk = blockIdx.x;
    const int b0 = blockIdx.y * 16;

    float acc[4] = {0.f, 0.f, 0.f, 0.f};

    const uint4* Wp = (const uint4*)Wswz
        + ((size_t)(nblk * 2 + wn) * k16Stride + chOff) * 64 + lane;

    // lane-fixed activation row (B-fragment col) and k-pair offset
    const int bcol = b0 + wb * 8 + (lane >> 2);
    const int kb = 2 * (lane & 3);
    const float* rA1 = A1 + (size_t)bcol * sA1;
    const float* rA2 = A2 + (size_t)bcol * sA2 - K1;  // index by global k directly

    float2 B0[2], B1[2];
    uint4 WH[2], WL[2];

    auto ldB = [&](int ch, float2& v0, float2& v1) {
        int k = ch * 16 + kb;
        const float* s = (k < K1) ? rA1 : rA2;
        v0 = *(const float2*)(s + k);
        v1 = *(const float2*)(s + k + 8);
    };

    // prologue: prefetch chunks 0,1
    ldB(0, B0[0], B1[0]);
    WH[0] = Wp[0];
    WL[0] = Wp[32];
    if (nch > 1) {
        ldB(1, B0[1], B1[1]);
        WH[1] = Wp[64];
        WL[1] = Wp[96];
    }

    for (int ch = 0; ch < nch; ++ch) {
        const int s = ch & 1;
        uint32_t bh0, bl0, bh1, bl1;
        cvt_hilo(B0[s].x, B0[s].y, bh0, bl0);
        cvt_hilo(B1[s].x, B1[s].y, bh1, bl1);
        mma_bf16(acc, WH[s], bh0, bh1);
        mma_bf16(acc, WL[s], bh0, bh1);
        mma_bf16(acc, WH[s], bl0, bl1);
        if (ch + 2 < nch) {
            ldB(ch + 2, B0[s], B1[s]);
            WH[s] = Wp[(size_t)(ch + 2) * 64];
            WL[s] = Wp[(size_t)(ch + 2) * 64 + 32];
        }
    }

    // ---- epilogue: transpose C fragments through shared (single sync) ----
    const int CP = 18;
    {
        int r = lane >> 2;
        int cc = 2 * (lane & 3);
        int nl = wn * 16 + r;
        int blc = wb * 8 + cc;
        sbuf[nl * CP + blc] = acc[0];
        sbuf[nl * CP + blc + 1] = acc[1];
        sbuf[(nl + 8) * CP + blc] = acc[2];
        sbuf[(nl + 8) * CP + blc + 1] = acc[3];
    }
    __syncthreads();

    if (MODE == 0) {
        // 8 gate-quads (j) x 16 batch = 128 -> one per thread
        int j = tid & 7, bl = tid >> 3;
        int jg = nblk * 8 + j;
        int b = b0 + bl;
        float e0 = 0.f, e1 = 0.f, e2 = 0.f, e3 = 0.f;
        if (extra) {
            const float* ep = extra + (size_t)(nblk * 32 + j * 4) * NB + b;
            e0 = ep[0]; e1 = ep[NB]; e2 = ep[2 * NB]; e3 = ep[3 * NB];
        }
        float gi = sbuf[(j * 4 + 0) * CP + bl] + bias[nblk * 32 + j * 4 + 0] + e0;
        float gf = sbuf[(j * 4 + 1) * CP + bl] + bias[nblk * 32 + j * 4 + 1] + e1;
        float gg = sbuf[(j * 4 + 2) * CP + bl] + bias[nblk * 32 + j * 4 + 2] + e2;
        float go = sbuf[(j * 4 + 3) * CP + bl] + bias[nblk * 32 + j * 4 + 3] + e3;
        float cold = cio[(size_t)b * NH + jg];
        float cn = sigf(gf) * cold + sigf(gi) * tanhf(gg);
        float hn = sigf(go) * tanhf(cn);
        cio[(size_t)b * NH + jg] = cn;
        outp[(size_t)b * sOut + jg] = hn;
        if (clipOut) clipOut[(size_t)b * NNIN + jg] = clipf(hn);
    } else if (MODE == 1) {
#pragma unroll
        for (int i = 0; i < 4; ++i) {
            int pair = i * 128 + tid;
            int n = pair & 31, bl = pair >> 5;
            int ng = nblk * 32 + n;
            if (ng < nReal) {
                int b = b0 + bl;
                outp[(size_t)b * sOut + ng] = sbuf[n * CP + bl] + bias[ng];
            }
        }
    } else {
        // MODE 2: x-precompute, batch index bg = b*NT + t -> [t][n'][b]
#pragma unroll
        for (int i = 0; i < 4; ++i) {
            int pair = i * 128 + tid;
            int n = pair & 31, bl = pair >> 5;
            int ng = nblk * 32 + n;
            int bg = b0 + bl;
            int t = bg & (NT - 1);
            int bi = bg >> 5;
            outp[((size_t)t * 2048 + ng) * NB + bi] = sbuf[n * CP + bl];
        }
    }
}

// ---------------- DNC memory step (iface precomputed) ------------------------
__global__ __launch_bounds__(128) void memstep(
    const float* __restrict__ ifcg,
    float* __restrict__ memg, float* __restrict__ linkg,
    float* __restrict__ precg, float* __restrict__ rwg,
    float* __restrict__ wwg, float* __restrict__ usg,
    float* __restrict__ inp)
{
    const int RS = 80, WK = 84, WS = 104, ER = 105, WV = 125,
              FG = 145, AG = 149, WG = 150, RM = 151;
    const int b = blockIdx.x;
    const int tid = threadIdx.x;

    __shared__ float ifc[NIF];
    __shared__ float sm[NM * NWC];
    __shared__ float sl[NM * NM];
    __shared__ float sp[NM], srw[NR * NM], sww[NM], sus[NM];
    __shared__ float wcw[NM], alo[NM];
    __shared__ float rcw[NR * NM], fwd[NR * NM], bwd[NR * NM];

    for (int i = tid; i < NIF; i += 128) ifc[i] = ifcg[b * NIFP + i];
    for (int i = tid; i < NM * NWC; i += 128) sm[i] = memg[b * NM * NWC + i];
    for (int i = tid; i < NM * NM; i += 128) sl[i] = linkg[b * NM * NM + i];
    if (tid < NM) {
        sp[tid] = precg[b * NM + tid];
        sww[tid] = wwg[b * NM + tid];
        sus[tid] = usg[b * NM + tid];
    }
    if (tid >= 32 && tid < 32 + NR * NM) srw[tid - 32] = rwg[b * NR * NM + tid - 32];
    __syncthreads();

    if (tid < NM) {
        int m = tid;
        float uu = sus[m] + (1.f - sus[m]) * sww[m];
        float psi = 1.f;
#pragma unroll
        for (int r = 0; r < NR; ++r)
            psi *= 1.f - sigf(ifc[FG + r]) * srw[r * NM + m];
        sus[m] = uu * psi;
    }
    __syncthreads();

    if (tid < NM) {
        int m = tid;
        float kn2 = 0.f, dot = 0.f, mn2 = 0.f;
#pragma unroll
        for (int w = 0; w < NWC; ++w) {
            float kv = tanhf(ifc[WK + w]);
            float mv = sm[m * NWC + w];
            kn2 = fmaf(kv, kv, kn2);
            mn2 = fmaf(mv, mv, mn2);
            dot = fmaf(kv, mv, dot);
        }
        wcw[m] = dot / ((sqrtf(kn2) + EPSF) * (sqrtf(mn2) + EPSF));
    }
    __syncthreads();
    if (tid == 0) {
        float str = softplusf(ifc[WS]);
        float mx = -1e30f;
        for (int m = 0; m < NM; ++m) { wcw[m] *= str; mx = fmaxf(mx, wcw[m]); }
        float s = 0.f;
        for (int m = 0; m < NM; ++m) { wcw[m] = expf(wcw[m] - mx); s += wcw[m]; }
        float inv = 1.f / s;
        for (int m = 0; m < NM; ++m) wcw[m] *= inv;
    }
    if (tid == 32) {
        float u[NM]; int idx[NM];
        for (int m = 0; m < NM; ++m) { u[m] = DELTAF + (1.f - DELTAF) * sus[m]; idx[m] = m; }
        for (int i = 1; i < NM; ++i) {
            float kv = u[i]; int ki = idx[i]; int j = i;
            while (j > 0 && u[j - 1] > kv) { u[j] = u[j - 1]; idx[j] = idx[j - 1]; --j; }
            u[j] = kv; idx[j] = ki;
        }
        float prod = 1.f;
        for (int j = 0; j < NM; ++j) { alo[idx[j]] = (1.f - u[j]) * prod; prod *= u[j]; }
    }
    __syncthreads();

    if (tid < NM) {
        float ag = sigf(ifc[AG]), wg = sigf(ifc[WG]);
        sww[tid] = wg * (ag * alo[tid] + (1.f - ag) * wcw[tid]);
    }
    __syncthreads();

    for (int i = tid; i < NM * NWC; i += 128) {
        int m = i / NWC, w = i % NWC;
        float e = sigf(ifc[ER + w]);
        float v = tanhf(ifc[WV + w]);
        sm[i] = sm[i] * (1.f - sww[m] * e) + sww[m] * v;
    }
    __syncthreads();

    for (int i = tid; i < NM * NM; i += 128) {
        int ii = i >> 4, jj = i & 15;
        sl[i] = (ii == jj) ? 0.f
                           : (1.f - sww[ii] - sww[jj]) * sl[i] + sww[ii] * sp[jj];
    }
    __syncthreads();

    if (tid < NM) {
        float s = 0.f;
#pragma unroll
        for (int m = 0; m < NM; ++m) s += sww[m];
        sp[tid] = (1.f - s) * sp[tid] + sww[tid];
    }
    __syncthreads();

    if (tid < NR * NM) {
        int r = tid >> 4, m = tid & 15;
        float kn2 = 0.f, dot = 0.f, mn2 = 0.f;
#pragma unroll
        for (int w = 0; w < NWC; ++w) {
            float kv = tanhf(ifc[r * NWC + w]);
            float mv = sm[m * NWC + w];
            kn2 = fmaf(kv, kv, kn2);
            mn2 = fmaf(mv, mv, mn2);
            dot = fmaf(kv, mv, dot);
        }
        rcw[tid] = dot / ((sqrtf(kn2) + EPSF) * (sqrtf(mn2) + EPSF));
    }
    __syncthreads();
    if (tid < NR) {
        int r = tid;
        float str = softplusf(ifc[RS + r]);
        float mx = -1e30f;
        for (int m = 0; m < NM; ++m) { rcw[r * NM + m] *= str; mx = fmaxf(mx, rcw[r * NM + m]); }
        float s = 0.f;
        for (int m = 0; m < NM; ++m) { rcw[r * NM + m] = expf(rcw[r * NM + m] - mx); s += rcw[r * NM + m]; }
        float inv = 1.f / s;
        for (int m = 0; m < NM; ++m) rcw[r * NM + m] *= inv;
    }
    __syncthreads();

    if (tid < NR * NM) {
        int r = tid >> 4, q = tid & 15;
        float f = 0.f, bb = 0.f;
#pragma unroll
        for (int j = 0; j < NM; ++j) {
            f = fmaf(sl[q * NM + j], srw[r * NM + j], f);
            bb = fmaf(srw[r * NM + j], sl[j * NM + q], bb);
        }
        fwd[tid] = f;
        bwd[tid] = bb;
    }
    __syncthreads();

    if (tid < NR * NM) {
        int r = tid >> 4;
        float e0 = ifc[RM + r * 3 + 0], e1 = ifc[RM + r * 3 + 1], e2 = ifc[RM + r * 3 + 2];
        float mx = fmaxf(e0, fmaxf(e1, e2));
        float x0 = expf(e0 - mx), x1 = expf(e1 - mx), x2 = expf(e2 - mx);
        float inv = 1.f / (x0 + x1 + x2);
        srw[tid] = (x0 * bwd[tid] + x1 * fwd[tid] + x2 * rcw[tid]) * inv;
    }
    __syncthreads();

    if (tid < NRW) {
        int r = tid / NWC, w = tid % NWC;
        float s = 0.f;
#pragma unroll
        for (int m = 0; m < NM; ++m) s = fmaf(srw[r * NM + m], sm[m * NWC + w], s);
        inp[(size_t)b * NNIN + NIN + tid] = s;
    }

    for (int i = tid; i < NM * NWC; i += 128) memg[b * NM * NWC + i] = sm[i];
    for (int i = tid; i < NM * NM; i += 128) linkg[b * NM * NM + i] = sl[i];
    if (tid < NM) {
        precg[b * NM + tid] = sp[tid];
        wwg[b * NM + tid] = sww[tid];
        usg[b * NM + tid] = sus[tid];
    }
    if (tid >= 32 && tid < 32 + NR * NM) rwg[b * NR * NM + tid - 32] = srw[tid - 32];
}

// ---------------- host driver ------------------------------------------------
extern "C" void kernel_launch(void* const* d_in, const int* in_sizes, int n_in,
                              void* d_out, int out_size)
{
    const float* x      = (const float*)d_in[0];
    const float* W_ih0  = (const float*)d_in[1];
    const float* W_hh0  = (const float*)d_in[2];
    const float* b_ih0  = (const float*)d_in[3];
    const float* b_hh0  = (const float*)d_in[4];
    const float* W_ih1  = (const float*)d_in[5];
    const float* W_hh1  = (const float*)d_in[6];
    const float* b_ih1  = (const float*)d_in[7];
    const float* b_hh1  = (const float*)d_in[8];
    const float* W_if   = (const float*)d_in[9];
    const float* b_if   = (const float*)d_in[10];
    const float* W_out  = (const float*)d_in[11];
    const float* b_out  = (const float*)d_in[12];
    float* y = (float*)d_out;

    float *ph, *pc, *pinp, *pifc, *pxp, *pmem, *plink, *pprec, *prw, *pww, *pus, *pbc;
    unsigned *pW00, *pW01, *pW10, *pW11, *pWif, *pWo;
    cudaGetSymbolAddress((void**)&ph,   g_h);
    cudaGetSymbolAddress((void**)&pc,   g_c);
    cudaGetSymbolAddress((void**)&pinp, g_inp);
    cudaGetSymbolAddress((void**)&pifc, g_ifc);
    cudaGetSymbolAddress((void**)&pxp,  g_xpart);
    cudaGetSymbolAddress((void**)&pmem, g_mem);
    cudaGetSymbolAddress((void**)&plink,g_link);
    cudaGetSymbolAddress((void**)&pprec,g_prec);
    cudaGetSymbolAddress((void**)&prw,  g_rw);
    cudaGetSymbolAddress((void**)&pww,  g_ww);
    cudaGetSymbolAddress((void**)&pus,  g_usage);
    cudaGetSymbolAddress((void**)&pW00, g_W00);
    cudaGetSymbolAddress((void**)&pW01, g_W01);
    cudaGetSymbolAddress((void**)&pW10, g_W10);
    cudaGetSymbolAddress((void**)&pW11, g_W11);
    cudaGetSymbolAddress((void**)&pWif, g_Wif);
    cudaGetSymbolAddress((void**)&pWo,  g_Wo);
    cudaGetSymbolAddress((void**)&pbc,  g_bc);

    auto hbuf = [&](int p, int l, int s) {
        return ph + (((size_t)p * 2 + l) * 2 + s) * NB * NH;
    };
    auto cbuf = [&](int l, int s) { return pc + ((size_t)l * 2 + s) * NB * NH; };

    initk<<<512, 256>>>();                                               // 0
    prepAll<<<dim3(1104, 7), 256>>>(W_ih0, W_hh0, W_ih1, W_hh1, W_if,    // 1
                                    W_out, pW00, pW01, pW10, pW11, pWif, pWo);
    prepbias<<<(2 * 2 * 2048 + 255) / 256, 256>>>(b_ih0, b_hh0,          // 2
                                                  b_ih1, b_hh1, pbc);
    // x-precompute: batch 4096 = b*NT + t, K=512, chunks 0..31 of W00
    tcgemm<2><<<dim3(64, 256), 128>>>(x, NIN, 512, x, NIN, 0,            // 3
                                      pW00, 64, 0, nullptr, 2048,
                                      nullptr, pxp, 0, nullptr, nullptr);

    const unsigned* Wc1[2] = {pW10, pW11};
    const dim3 gCell(64, 8);
    const dim3 gIf(6, 8);
    const dim3 gOut(16, 8);

    for (int t = 0; t < NT; ++t) {
        const int p = t & 1;
        for (int l = 0; l < 2; ++l) {
            // ---- cell 0 ----
            if (l == 0) {
                // K=512 (hidden only) + precomputed x-partial
                tcgemm<0><<<gCell, 128>>>(
                    hbuf(p, 0, 0), NH, 512, hbuf(p, 0, 0), NH, 0,
                    pW00, 64, 32,
                    pbc, 2048,
                    cbuf(0, 0),
                    hbuf(p ^ 1, 0, 0), NH,
                    nullptr,
                    pxp + (size_t)t * 2048 * NB);
            } else {
                tcgemm<0><<<gCell, 128>>>(
                    pinp, NNIN, 592, hbuf(p, 1, 0), NH, 512,
                    pW01, 69, 0,
                    pbc + (size_t)2 * 2048, 2048,
                    cbuf(1, 0),
                    hbuf(p ^ 1, 1, 0), NH,
                    nullptr, nullptr);
            }
            // ---- cell 1 ----
            tcgemm<0><<<gCell, 128>>>(
                hbuf(p ^ 1, l, 0), NH, 512, hbuf(p, l, 1), NH, 512,
                Wc1[l], 64, 0,
                pbc + (size_t)(l * 2 + 1) * 2048, 2048,
                cbuf(l, 1),
                hbuf(p ^ 1, l, 1), NH,
                pinp, nullptr);
            // ---- iface projection ----
            tcgemm<1><<<gIf, 128>>>(
                pinp, NNIN, 512, pinp, NNIN, 0,
                pWif + (size_t)l * 12 * 32 * 256, 32, 0,
                b_if + (size_t)l * NIF, NIF,
                nullptr, pifc, NIFP, nullptr, nullptr);
            // ---- memory step ----
            memstep<<<NB, 128>>>(
                pifc,
                pmem + (size_t)l * NB * NM * NWC,
                plink + (size_t)l * NB * NM * NM,
                pprec + (size_t)l * NB * NM,
                prw + (size_t)l * NB * NR * NM,
                pww + (size_t)l * NB * NM,
                pus + (size_t)l * NB * NM,
                pinp);
        }
        // ---- output projection ----
        tcgemm<1><<<gOut, 128>>>(
            pinp, NNIN, 592, pinp, NNIN, 0,
            pWo, 37, 0,
            b_out, 512,
            nullptr, y + (size_t)t * NIN, NT * NIN, nullptr, nullptr);
    }
}